// round 13
// baseline (speedup 1.0000x reference)
#include <cuda_runtime.h>
#include <cuda_fp16.h>
#include <cstdint>
#include <math.h>

#define BBAT 2
#define LL   2048
#define DD   1024
#define HH   16
#define DHD  64
#define DFFN 4096
#define MTOT (BBAT*LL)   // 4096

// ---- scratch (__device__ globals; no allocation allowed) ----
__device__ __half g_qk  [(size_t)MTOT*2*DD];          // Q|K fp16 perm16
__device__ __half g_vt  [(size_t)BBAT*HH*DHD*LL];     // V^T fp16 perm16(l)
__device__ __half g_attn[(size_t)MTOT*DD];
__device__ float  g_t0  [(size_t)MTOT*DD];
__device__ float  g_h1  [(size_t)MTOT*DD];
__device__ __half g_h1r [(size_t)MTOT*DD];
__device__ __half g_ffn [(size_t)MTOT*DFFN];
__device__ __half g_xr  [(size_t)MTOT*DD];
__device__ __half g_wqkvr[(size_t)3*DD*DD];
__device__ __half g_wor [(size_t)DD*DD];
__device__ __half g_w1r [(size_t)DFFN*DD];
__device__ __half g_w2r [(size_t)DD*DFFN];

// ============================================================
// Helpers
// ============================================================
__device__ __forceinline__ void mma16h(float* c, uint32_t a0, uint32_t a1,
                                       uint32_t a2, uint32_t a3,
                                       uint32_t b0, uint32_t b1) {
    asm volatile(
        "mma.sync.aligned.m16n8k16.row.col.f32.f16.f16.f32 "
        "{%0,%1,%2,%3}, {%4,%5,%6,%7}, {%8,%9}, {%0,%1,%2,%3};\n"
        : "+f"(c[0]), "+f"(c[1]), "+f"(c[2]), "+f"(c[3])
        : "r"(a0), "r"(a1), "r"(a2), "r"(a3), "r"(b0), "r"(b1));
}
__device__ __forceinline__ void cp_async16(uint32_t dst, const void* src) {
    asm volatile("cp.async.cg.shared.global [%0], [%1], 16;\n" :: "r"(dst), "l"(src));
}
__device__ __forceinline__ void cp_commit() { asm volatile("cp.async.commit_group;\n"); }
template<int N> __device__ __forceinline__ void cp_wait() {
    asm volatile("cp.async.wait_group %0;\n" :: "n"(N));
}
// fp16 16-group permuted index: order [0,1,8,9,2,3,10,11,4,5,12,13,6,7,14,15]
__device__ __forceinline__ int p16(int c) {
    return ((c & 7) >> 1) * 4 + ((c >> 3) & 1) * 2 + (c & 1);
}
__device__ __forceinline__ uint32_t h2u(__half2 h) {
    return *reinterpret_cast<uint32_t*>(&h);
}

// ============================================================
// fp32 -> fp16 convert + permute into 16-groups
// ============================================================
__global__ void __launch_bounds__(256) round_perm16(
    const float* __restrict__ in, __half* __restrict__ out, int n16)
{
    int i = blockIdx.x * 256 + threadIdx.x;
    if (i < n16) {
        const float4* src = (const float4*)(in + (size_t)i * 16);
        float4 v0 = src[0], v1 = src[1], v2 = src[2], v3 = src[3];
        uint4 o0, o1;
        o0.x = h2u(__floats2half2_rn(v0.x, v0.y));
        o0.y = h2u(__floats2half2_rn(v2.x, v2.y));
        o0.z = h2u(__floats2half2_rn(v0.z, v0.w));
        o0.w = h2u(__floats2half2_rn(v2.z, v2.w));
        o1.x = h2u(__floats2half2_rn(v1.x, v1.y));
        o1.y = h2u(__floats2half2_rn(v3.x, v3.y));
        o1.z = h2u(__floats2half2_rn(v1.z, v1.w));
        o1.w = h2u(__floats2half2_rn(v3.z, v3.w));
        uint4* dst = (uint4*)(out + (size_t)i * 16);
        dst[0] = o0; dst[1] = o1;
    }
}

// ============================================================
// FP16 mma GEMM, pre-permuted operands. Warp tile 64x64 (4 warps,
// 128 threads, 2 CTAs/SM) to cut smem crossbar bytes per MMA.
// OUT: 0 = fp32, 1 = fp16 perm16, 2 = QKV split (Q/K perm16 + V^T)
// 4-slot cp.async ring, lookahead 3, one syncthreads pair per tile.
// ============================================================
#define BK 32
#define NSLOT 4
#define STAGE_B 16384
#define GEMM_SMEM (NSLOT * STAGE_B)        // 65536
#define GT 128                             // gemm threads

template<bool RELU, bool RES, int OUT>
__global__ void __launch_bounds__(GT, 2) gemm_h(
    const __half* __restrict__ A, const __half* __restrict__ W,
    const float* __restrict__ bias, const float* __restrict__ res,
    void* __restrict__ Cv, __half* __restrict__ QKo, __half* __restrict__ VTo,
    int M, int N, int K)
{
    extern __shared__ char smem[];
    const uint32_t sbase = (uint32_t)__cvta_generic_to_shared(smem);

    const int tid = threadIdx.x;
    const int lane = tid & 31, wid = tid >> 5;
    const int bm = blockIdx.y * 128, bn = blockIdx.x * 128;
    const int wm = (wid >> 1) * 64;
    const int wn = (wid & 1) * 64;
    const int gid = lane >> 2, tig = lane & 3;
    const int kap = (gid >> 1) & 1;
    const int T = K / BK;

    float acc[4][8][4];
#pragma unroll
    for (int mi = 0; mi < 4; mi++)
#pragma unroll
        for (int ni = 0; ni < 8; ni++)
#pragma unroll
            for (int r = 0; r < 4; r++) acc[mi][ni][r] = 0.f;

    auto load_tile = [&](int t, int slot) {
        const uint32_t st = sbase + (uint32_t)slot * STAGE_B;
        const int kt = t * BK;
#pragma unroll
        for (int i = 0; i < 4; i++) {       // A: 512 chunks of 16B
            int c = tid + i * GT;
            int r = c >> 2, h = c & 3, g = h >> 1;
            uint32_t dst = st + (uint32_t)(r * 64 + ((g ^ ((r >> 1) & 1)) * 32) + (h & 1) * 16);
            cp_async16(dst, A + (size_t)(bm + r) * K + kt + h * 8);
        }
        const uint32_t stb = st + 8192;
#pragma unroll
        for (int i = 0; i < 4; i++) {       // B: 512 chunks
            int c = tid + i * GT;
            int r = c >> 2, h = c & 3, g = h >> 1;
            uint32_t dst = stb + (uint32_t)(r * 64 + ((g ^ ((r >> 1) & 1)) * 32) + (h & 1) * 16);
            cp_async16(dst, W + (size_t)(bn + r) * K + kt + h * 8);
        }
    };

    load_tile(0, 0); cp_commit();
    load_tile(1, 1); cp_commit();
    load_tile(2, 2); cp_commit();

    for (int t = 0; t < T; t++) {
        cp_wait<2>();
        __syncthreads();
        if (t + 3 < T) load_tile(t + 3, (t + 3) & 3);
        cp_commit();

        const __half* Ah = (const __half*)(smem + (size_t)(t & 3) * STAGE_B);
        const __half* Bh = Ah + 128 * 32;
#pragma unroll
        for (int grp = 0; grp < 2; grp++) {
            const int off = ((grp ^ kap) * 16) + tig * 4;
            uint2 fa[4][2];
#pragma unroll
            for (int mi = 0; mi < 4; mi++) {
                const int r = wm + mi * 16 + gid;
                fa[mi][0] = *(const uint2*)(Ah + r * 32 + off);
                fa[mi][1] = *(const uint2*)(Ah + (r + 8) * 32 + off);
            }
            uint2 fb[8];
#pragma unroll
            for (int ni = 0; ni < 8; ni++)
                fb[ni] = *(const uint2*)(Bh + (wn + ni * 8 + gid) * 32 + off);
#pragma unroll
            for (int mi = 0; mi < 4; mi++)
#pragma unroll
                for (int ni = 0; ni < 8; ni++)
                    mma16h(acc[mi][ni],
                           fa[mi][0].x, fa[mi][1].x, fa[mi][0].y, fa[mi][1].y,
                           fb[ni].x, fb[ni].y);
        }
        __syncthreads();
    }

    // epilogue
#pragma unroll
    for (int ni = 0; ni < 8; ni++) {
        const int cb = bn + wn + ni * 8;
        const int c0 = 2 * tig, c1 = 2 * tig + 1;
        const float b0 = bias[cb + c0], b1 = bias[cb + c1];
#pragma unroll
        for (int mi = 0; mi < 4; mi++) {
            const int row = bm + wm + mi * 16 + gid;
#pragma unroll
            for (int rr = 0; rr < 2; rr++) {
                const int r = row + rr * 8;
                float v0 = acc[mi][ni][rr * 2 + 0] + b0;
                float v1 = acc[mi][ni][rr * 2 + 1] + b1;
                size_t off = (size_t)r * N + cb + c0;
                if (RES) { v0 += res[off]; v1 += res[off + 1]; }
                if (RELU) { v0 = fmaxf(v0, 0.f); v1 = fmaxf(v1, 0.f); }
                if (OUT == 0) {
                    float2 o; o.x = v0; o.y = v1;
                    *(float2*)&((float*)Cv)[off] = o;
                } else if (OUT == 1) {
                    __half* C16 = (__half*)Cv;
                    int col0 = cb + c0;
                    size_t idx = (size_t)r * N + (col0 & ~15) + p16(col0 & 15);
                    *(__half2*)&C16[idx] = __floats2half2_rn(v0, v1);
                } else {
                    int col0 = cb + c0;
                    __half h0 = __float2half_rn(v0), h1v = __float2half_rn(v1);
                    if (col0 < 2048) {
                        size_t idx = (size_t)r * 2048 + (col0 & ~15) + p16(col0 & 15);
                        *(__half2*)&QKo[idx] = __halves2half2(h0, h1v);
                    } else {
                        int d0 = col0 - 2048;
                        int hd = d0 >> 6, dh = d0 & 63;
                        int b_ = r >> 11, l = r & 2047;
                        size_t lidx = (size_t)(l & ~15) + p16(l & 15);
                        size_t rowb = ((size_t)(b_ * HH + hd) * DHD + dh) * LL;
                        VTo[rowb + lidx]      = h0;
                        VTo[rowb + LL + lidx] = h1v;   // dh+1 (dh even)
                    }
                }
            }
        }
    }
}

// ============================================================
// FP16 tensor-core causal flash attention. (unchanged from R11)
// ============================================================
#define AQ 128

__global__ void __launch_bounds__(256) attn_h(
    const __half* __restrict__ qk, const __half* __restrict__ vt,
    __half* __restrict__ O)
{
    __shared__ __half Qs[128 * 64];
    __shared__ __half Ks[2][32 * 64];
    __shared__ __half Vts[2][64 * 32];
    __shared__ __half Ps[128 * 32];

    const int qi = blockIdx.x, h = blockIdx.y, b = blockIdx.z;
    const int tid = threadIdx.x, lane = tid & 31, wid = tid >> 5;
    const int gid = lane >> 2, tig = lane & 3;

    const uint32_t sQ = (uint32_t)__cvta_generic_to_shared(Qs);
    const uint32_t sK = (uint32_t)__cvta_generic_to_shared(Ks);
    const uint32_t sV = (uint32_t)__cvta_generic_to_shared(Vts);

    const __half* qbQ = qk + ((size_t)(b * LL + qi * AQ)) * 2048 + h * 64;
    const __half* qbK = qk + ((size_t)(b * LL)) * 2048 + 1024 + h * 64;
    const __half* vb  = vt + ((size_t)(b * HH + h) * DHD) * LL;

#pragma unroll
    for (int i = 0; i < 4; i++) {
        int c = tid + i * 256;
        int r = c >> 3, ch = c & 7;
        uint32_t dst = sQ + (uint32_t)(r * 128 + (((ch >> 1) ^ (r & 3)) * 32) + (ch & 1) * 16);
        cp_async16(dst, qbQ + (size_t)r * 2048 + ch * 8);
    }
    auto load_kv = [&](int kt, int slot) {
        {
            int r = tid >> 3, ch = tid & 7;
            uint32_t dst = sK + (uint32_t)(slot * 4096 + r * 128 + (((ch >> 1) ^ (r & 3)) * 32) + (ch & 1) * 16);
            cp_async16(dst, qbK + (size_t)(kt * 32 + r) * 2048 + ch * 8);
        }
        {
            int d = tid >> 2, ch = tid & 3;
            uint32_t dst = sV + (uint32_t)(slot * 4096 + d * 64 + (((ch >> 1) ^ ((d >> 1) & 1)) * 32) + (ch & 1) * 16);
            cp_async16(dst, vb + (size_t)d * LL + kt * 32 + ch * 8);
        }
    };
    load_kv(0, 0); cp_commit();

    float m0 = -1e30f, m1 = -1e30f, l0 = 0.f, l1 = 0.f;
    float oacc[8][4];
#pragma unroll
    for (int ni = 0; ni < 8; ni++)
#pragma unroll
        for (int c = 0; c < 4; c++) oacc[ni][c] = 0.f;

    const int r0 = 16 * wid + gid;
    const int rowg0 = qi * AQ + r0, rowg1 = rowg0 + 8;
    const int keyQ = r0 & 3;
    const int keyP = (r0 >> 1) & 1;
    const int ktmax = 4 * qi + 3;

    for (int kt = 0; kt <= ktmax; kt++) {
        cp_wait<0>();
        __syncthreads();
        if (kt + 1 <= ktmax) load_kv(kt + 1, (kt + 1) & 1);
        cp_commit();

        const __half* Kt  = Ks[kt & 1];
        const __half* Vtt = Vts[kt & 1];

        float sfr[4][4];
#pragma unroll
        for (int ni = 0; ni < 4; ni++)
#pragma unroll
            for (int c = 0; c < 4; c++) sfr[ni][c] = 0.f;
#pragma unroll
        for (int grp = 0; grp < 4; grp++) {
            const __half* qa = Qs + r0 * 64 + ((grp ^ keyQ) * 16) + tig * 4;
            uint2 fa0 = *(const uint2*)qa;
            uint2 fa1 = *(const uint2*)(qa + 8 * 64);
#pragma unroll
            for (int ni = 0; ni < 4; ni++) {
                int kk = 8 * ni + gid;
                uint2 fb = *(const uint2*)(Kt + kk * 64 + ((grp ^ (kk & 3)) * 16) + tig * 4);
                mma16h(sfr[ni], fa0.x, fa1.x, fa0.y, fa1.y, fb.x, fb.y);
            }
        }

        const bool domask = (kt >= 4 * qi);
        const int colbase = kt * 32;
        float p[4][4];
#pragma unroll
        for (int ni = 0; ni < 4; ni++)
#pragma unroll
            for (int c = 0; c < 4; c++) {
                float v = sfr[ni][c] * 0.125f;
                if (domask) {
                    int col = colbase + 8 * ni + 2 * tig + (c & 1);
                    int rg = (c < 2) ? rowg0 : rowg1;
                    if (col > rg) v = -1e30f;
                }
                p[ni][c] = v;
            }
#pragma unroll
        for (int half = 0; half < 2; half++) {
            float rmax = -1e30f;
#pragma unroll
            for (int ni = 0; ni < 4; ni++) {
                rmax = fmaxf(rmax, p[ni][half * 2]);
                rmax = fmaxf(rmax, p[ni][half * 2 + 1]);
            }
            rmax = fmaxf(rmax, __shfl_xor_sync(0xffffffffu, rmax, 1));
            rmax = fmaxf(rmax, __shfl_xor_sync(0xffffffffu, rmax, 2));
            float mprev = half ? m1 : m0;
            float mn = fmaxf(mprev, rmax);
            float alpha = __expf(mprev - mn);
            float psum = 0.f;
#pragma unroll
            for (int ni = 0; ni < 4; ni++) {
#pragma unroll
                for (int j = 0; j < 2; j++) {
                    float e = __expf(p[ni][half * 2 + j] - mn);
                    p[ni][half * 2 + j] = e;
                    psum += e;
                }
            }
            psum += __shfl_xor_sync(0xffffffffu, psum, 1);
            psum += __shfl_xor_sync(0xffffffffu, psum, 2);
            if (half == 0) { l0 = l0 * alpha + psum; m0 = mn; }
            else           { l1 = l1 * alpha + psum; m1 = mn; }
#pragma unroll
            for (int ni = 0; ni < 8; ni++) {
                oacc[ni][half * 2]     *= alpha;
                oacc[ni][half * 2 + 1] *= alpha;
            }
        }

#pragma unroll
        for (int ni = 0; ni < 4; ni++) {
            int g16 = ni >> 1;
            int off0 = r0 * 32 + ((g16 ^ keyP) * 16) + 4 * tig + 2 * (ni & 1);
            *(__half2*)(Ps + off0)          = __floats2half2_rn(p[ni][0], p[ni][1]);
            *(__half2*)(Ps + off0 + 8 * 32) = __floats2half2_rn(p[ni][2], p[ni][3]);
        }
        __syncwarp();

#pragma unroll
        for (int grp = 0; grp < 2; grp++) {
            const __half* pa = Ps + r0 * 32 + ((grp ^ keyP) * 16) + tig * 4;
            uint2 fa0 = *(const uint2*)pa;
            uint2 fa1 = *(const uint2*)(pa + 8 * 32);
#pragma unroll
            for (int ni = 0; ni < 8; ni++) {
                int dd = 8 * ni + gid;
                uint2 fb = *(const uint2*)(Vtt + dd * 32 + ((grp ^ ((dd >> 1) & 1)) * 16) + tig * 4);
                mma16h(oacc[ni], fa0.x, fa1.x, fa0.y, fa1.y, fb.x, fb.y);
            }
        }
    }

    float inv0 = 1.0f / l0, inv1 = 1.0f / l1;
    size_t ob0 = ((size_t)(b * LL + rowg0) * HH + h) * DHD;
    size_t ob1 = ((size_t)(b * LL + rowg1) * HH + h) * DHD;
#pragma unroll
    for (int ni = 0; ni < 8; ni++) {
        int dcol = 8 * ni + 2 * tig;
        int pos = (dcol & ~15) + p16(dcol & 15);
        *(__half2*)&O[ob0 + pos] = __floats2half2_rn(oacc[ni][0] * inv0, oacc[ni][1] * inv0);
        *(__half2*)&O[ob1 + pos] = __floats2half2_rn(oacc[ni][2] * inv1, oacc[ni][3] * inv1);
    }
}

// ============================================================
// LayerNorm (ddof=1, (std+eps)); optional fp16-permuted 2nd output
// ============================================================
__global__ void __launch_bounds__(256) ln_kernel(
    const float* __restrict__ X, const float* __restrict__ gamma,
    const float* __restrict__ beta, float* __restrict__ Y,
    __half* __restrict__ Yr)
{
    const int row = blockIdx.x;
    const int tid = threadIdx.x;
    const int lane = tid & 31, wid = tid >> 5;
    __shared__ float red[8];

    float4 v = *(const float4*)&X[(size_t)row * DD + tid * 4];

    float s = v.x + v.y + v.z + v.w;
#pragma unroll
    for (int off = 16; off > 0; off >>= 1) s += __shfl_xor_sync(0xffffffffu, s, off);
    if (lane == 0) red[wid] = s;
    __syncthreads();
    float mean = 0.f;
#pragma unroll
    for (int i = 0; i < 8; i++) mean += red[i];
    mean *= (1.0f / 1024.f);
    __syncthreads();

    float dx = v.x - mean, dy = v.y - mean, dz = v.z - mean, dw = v.w - mean;
    float ss = dx*dx + dy*dy + dz*dz + dw*dw;
#pragma unroll
    for (int off = 16; off > 0; off >>= 1) ss += __shfl_xor_sync(0xffffffffu, ss, off);
    if (lane == 0) red[wid] = ss;
    __syncthreads();
    float var = 0.f;
#pragma unroll
    for (int i = 0; i < 8; i++) var += red[i];
    var *= (1.0f / 1023.f);
    float istd = 1.0f / (sqrtf(var) + 1e-6f);

    float4 g  = *(const float4*)&gamma[tid * 4];
    float4 bb = *(const float4*)&beta[tid * 4];
    float o[4];
    o[0] = dx * istd * g.x + bb.x;
    o[1] = dy * istd * g.y + bb.y;
    o[2] = dz * istd * g.z + bb.z;
    o[3] = dw * istd * g.w + bb.w;
    float4 outv; outv.x = o[0]; outv.y = o[1]; outv.z = o[2]; outv.w = o[3];
    *(float4*)&Y[(size_t)row * DD + tid * 4] = outv;
    if (Yr) {
        __half* yr = Yr + (size_t)row * DD;
#pragma unroll
        for (int e = 0; e < 4; e++) {
            int col = tid * 4 + e;
            yr[(col & ~15) + p16(col & 15)] = __float2half_rn(o[e]);
        }
    }
}

// ============================================================
extern "C" void kernel_launch(void* const* d_in, const int* in_sizes, int n_in,
                              void* d_out, int out_size)
{
    const float* x     = (const float*)d_in[0];
    const float* Wqkv  = (const float*)d_in[2];
    const float* bqkv  = (const float*)d_in[3];
    const float* Wo    = (const float*)d_in[4];
    const float* bo    = (const float*)d_in[5];
    const float* ln1_a = (const float*)d_in[6];
    const float* ln1_b = (const float*)d_in[7];
    const float* W1    = (const float*)d_in[8];
    const float* b1    = (const float*)d_in[9];
    const float* W2    = (const float*)d_in[10];
    const float* b2    = (const float*)d_in[11];
    const float* ln2_a = (const float*)d_in[12];
    const float* ln2_b = (const float*)d_in[13];
    float* out = (float*)d_out;

    float  *t0, *h1;
    __half *qkb, *vtb, *attn, *h1r, *ffn, *xr, *wqkvr, *wor, *w1r, *w2r;
    cudaGetSymbolAddress((void**)&qkb,   g_qk);
    cudaGetSymbolAddress((void**)&vtb,   g_vt);
    cudaGetSymbolAddress((void**)&attn,  g_attn);
    cudaGetSymbolAddress((void**)&t0,    g_t0);
    cudaGetSymbolAddress((void**)&h1,    g_h1);
    cudaGetSymbolAddress((void**)&h1r,   g_h1r);
    cudaGetSymbolAddress((void**)&ffn,   g_ffn);
    cudaGetSymbolAddress((void**)&xr,    g_xr);
    cudaGetSymbolAddress((void**)&wqkvr, g_wqkvr);
    cudaGetSymbolAddress((void**)&wor,   g_wor);
    cudaGetSymbolAddress((void**)&w1r,   g_w1r);
    cudaGetSymbolAddress((void**)&w2r,   g_w2r);

    cudaFuncSetAttribute(gemm_h<false,false,2>, cudaFuncAttributeMaxDynamicSharedMemorySize, GEMM_SMEM);
    cudaFuncSetAttribute(gemm_h<false,true ,0>, cudaFuncAttributeMaxDynamicSharedMemorySize, GEMM_SMEM);
    cudaFuncSetAttribute(gemm_h<true ,false,1>, cudaFuncAttributeMaxDynamicSharedMemorySize, GEMM_SMEM);

    dim3 blk(256);
    dim3 gblk(GT);

    // convert+permute all GEMM A/B operands to fp16 16-groups
    round_perm16<<<(MTOT*DD/16 + 255)/256, blk>>>(x, xr, MTOT*DD/16);
    round_perm16<<<(3*DD*DD/16 + 255)/256, blk>>>(Wqkv, wqkvr, 3*DD*DD/16);
    round_perm16<<<(DD*DD/16 + 255)/256, blk>>>(Wo, wor, DD*DD/16);
    round_perm16<<<(DFFN*DD/16 + 255)/256, blk>>>(W1, w1r, DFFN*DD/16);
    round_perm16<<<(DD*DFFN/16 + 255)/256, blk>>>(W2, w2r, DD*DFFN/16);

    // 1) QKV GEMM: Q/K -> g_qk (fp16 perm16), V -> g_vt (fp16 transposed)
    gemm_h<false,false,2><<<dim3(3072/128, MTOT/128), gblk, GEMM_SMEM>>>(
        xr, wqkvr, bqkv, nullptr, nullptr, qkb, vtb, MTOT, 3*DD, DD);

    // 2) fp16 tensor-core causal flash attention -> attn (fp16 perm16)
    attn_h<<<dim3(LL/AQ, HH, BBAT), blk>>>(qkb, vtb, attn);

    // 3) t0 = attn @ Wo^T + bo + x (fp32 out)
    gemm_h<false,true,0><<<dim3(DD/128, MTOT/128), gblk, GEMM_SMEM>>>(
        attn, wor, bo, x, t0, nullptr, nullptr, MTOT, DD, DD);

    // 4) h1 = LN1(t0) fp32, h1r fp16 perm16
    ln_kernel<<<MTOT, blk>>>(t0, ln1_a, ln1_b, h1, h1r);

    // 5) ffn = relu(h1r @ W1^T + b1) (fp16 perm16 out)
    gemm_h<true,false,1><<<dim3(DFFN/128, MTOT/128), gblk, GEMM_SMEM>>>(
        h1r, w1r, b1, nullptr, ffn, nullptr, nullptr, MTOT, DFFN, DD);

    // 6) t0 = ffn @ W2^T + b2 + h1 (fp32 out)
    gemm_h<false,true,0><<<dim3(DD/128, MTOT/128), gblk, GEMM_SMEM>>>(
        ffn, w2r, b2, h1, t0, nullptr, nullptr, MTOT, DD, DFFN);

    // 7) out = LN2(t0)
    ln_kernel<<<MTOT, blk>>>(t0, ln2_a, ln2_b, out, nullptr);
}

// round 15
// speedup vs baseline: 1.5046x; 1.5046x over previous
#include <cuda_runtime.h>
#include <cuda_fp16.h>
#include <cstdint>
#include <math.h>

#define BBAT 2
#define LL   2048
#define DD   1024
#define HH   16
#define DHD  64
#define DFFN 4096
#define MTOT (BBAT*LL)   // 4096

// ---- scratch (__device__ globals; no allocation allowed) ----
__device__ __half g_qk  [(size_t)MTOT*2*DD];          // Q|K fp16 perm16
__device__ __half g_vt  [(size_t)BBAT*HH*DHD*LL];     // V^T fp16 perm16(l)
__device__ __half g_attn[(size_t)MTOT*DD];
__device__ float  g_t0  [(size_t)MTOT*DD];
__device__ float  g_h1  [(size_t)MTOT*DD];
__device__ __half g_h1r [(size_t)MTOT*DD];
__device__ __half g_ffn [(size_t)MTOT*DFFN];
__device__ __half g_xr  [(size_t)MTOT*DD];
__device__ __half g_wqkvr[(size_t)3*DD*DD];
__device__ __half g_wor [(size_t)DD*DD];
__device__ __half g_w1r [(size_t)DFFN*DD];
__device__ __half g_w2r [(size_t)DD*DFFN];

// ============================================================
// Helpers
// ============================================================
__device__ __forceinline__ void mma16h(float* c, uint32_t a0, uint32_t a1,
                                       uint32_t a2, uint32_t a3,
                                       uint32_t b0, uint32_t b1) {
    asm volatile(
        "mma.sync.aligned.m16n8k16.row.col.f32.f16.f16.f32 "
        "{%0,%1,%2,%3}, {%4,%5,%6,%7}, {%8,%9}, {%0,%1,%2,%3};\n"
        : "+f"(c[0]), "+f"(c[1]), "+f"(c[2]), "+f"(c[3])
        : "r"(a0), "r"(a1), "r"(a2), "r"(a3), "r"(b0), "r"(b1));
}
__device__ __forceinline__ void cp_async16(uint32_t dst, const void* src) {
    asm volatile("cp.async.cg.shared.global [%0], [%1], 16;\n" :: "r"(dst), "l"(src));
}
__device__ __forceinline__ void cp_commit() { asm volatile("cp.async.commit_group;\n"); }
template<int N> __device__ __forceinline__ void cp_wait() {
    asm volatile("cp.async.wait_group %0;\n" :: "n"(N));
}
// fp16 16-group permuted index: order [0,1,8,9,2,3,10,11,4,5,12,13,6,7,14,15]
__device__ __forceinline__ int p16(int c) {
    return ((c & 7) >> 1) * 4 + ((c >> 3) & 1) * 2 + (c & 1);
}
__device__ __forceinline__ uint32_t h2u(__half2 h) {
    return *reinterpret_cast<uint32_t*>(&h);
}

// ============================================================
// fp32 -> fp16 convert + permute into 16-groups (2 groups/thread)
// ============================================================
__global__ void __launch_bounds__(256) round_perm16(
    const float* __restrict__ in, __half* __restrict__ out, int n16)
{
    int i0 = blockIdx.x * 512 + threadIdx.x;
#pragma unroll
    for (int k = 0; k < 2; k++) {
        int i = i0 + k * 256;
        if (i < n16) {
            const float4* src = (const float4*)(in + (size_t)i * 16);
            float4 v0 = src[0], v1 = src[1], v2 = src[2], v3 = src[3];
            uint4 o0, o1;
            o0.x = h2u(__floats2half2_rn(v0.x, v0.y));
            o0.y = h2u(__floats2half2_rn(v2.x, v2.y));
            o0.z = h2u(__floats2half2_rn(v0.z, v0.w));
            o0.w = h2u(__floats2half2_rn(v2.z, v2.w));
            o1.x = h2u(__floats2half2_rn(v1.x, v1.y));
            o1.y = h2u(__floats2half2_rn(v3.x, v3.y));
            o1.z = h2u(__floats2half2_rn(v1.z, v1.w));
            o1.w = h2u(__floats2half2_rn(v3.z, v3.w));
            uint4* dst = (uint4*)(out + (size_t)i * 16);
            dst[0] = o0; dst[1] = o1;
        }
    }
}

// ============================================================
// FP16 mma GEMM on pre-permuted operands. (R11 config: 256 thr,
// warp 64x32, 2 CTAs/SM; 4-slot ring, lookahead 3, ONE barrier/tile)
// OUT: 0 = fp32, 1 = fp16 perm16, 2 = QKV split (Q/K perm16 + V^T)
// ============================================================
#define BK 32
#define NSLOT 4
#define STAGE_B 16384
#define GEMM_SMEM (NSLOT * STAGE_B)        // 65536

template<bool RELU, bool RES, int OUT>
__global__ void __launch_bounds__(256, 2) gemm_h(
    const __half* __restrict__ A, const __half* __restrict__ W,
    const float* __restrict__ bias, const float* __restrict__ res,
    void* __restrict__ Cv, __half* __restrict__ QKo, __half* __restrict__ VTo,
    int M, int N, int K)
{
    extern __shared__ char smem[];
    const uint32_t sbase = (uint32_t)__cvta_generic_to_shared(smem);

    const int tid = threadIdx.x;
    const int lane = tid & 31, wid = tid >> 5;
    const int bm = blockIdx.y * 128, bn = blockIdx.x * 128;
    const int wm = (wid >> 2) * 64;
    const int wn = (wid & 3) * 32;
    const int gid = lane >> 2, tig = lane & 3;
    const int kap = (gid >> 1) & 1;
    const int T = K / BK;

    float acc[4][4][4];
#pragma unroll
    for (int mi = 0; mi < 4; mi++)
#pragma unroll
        for (int ni = 0; ni < 4; ni++)
#pragma unroll
            for (int r = 0; r < 4; r++) acc[mi][ni][r] = 0.f;

    auto load_tile = [&](int t, int slot) {
        const uint32_t st = sbase + (uint32_t)slot * STAGE_B;
        const int kt = t * BK;
#pragma unroll
        for (int i = 0; i < 2; i++) {
            int c = tid + i * 256;
            int r = c >> 2, h = c & 3, g = h >> 1;
            uint32_t dst = st + (uint32_t)(r * 64 + ((g ^ ((r >> 1) & 1)) * 32) + (h & 1) * 16);
            cp_async16(dst, A + (size_t)(bm + r) * K + kt + h * 8);
        }
        const uint32_t stb = st + 8192;
#pragma unroll
        for (int i = 0; i < 2; i++) {
            int c = tid + i * 256;
            int r = c >> 2, h = c & 3, g = h >> 1;
            uint32_t dst = stb + (uint32_t)(r * 64 + ((g ^ ((r >> 1) & 1)) * 32) + (h & 1) * 16);
            cp_async16(dst, W + (size_t)(bn + r) * K + kt + h * 8);
        }
    };

    load_tile(0, 0); cp_commit();
    load_tile(1, 1); cp_commit();
    load_tile(2, 2); cp_commit();

    for (int t = 0; t < T; t++) {
        cp_wait<2>();
        __syncthreads();     // single barrier per tile: orders slot reuse AND data visibility
        if (t + 3 < T) load_tile(t + 3, (t + 3) & 3);
        cp_commit();

        const __half* Ah = (const __half*)(smem + (size_t)(t & 3) * STAGE_B);
        const __half* Bh = Ah + 128 * 32;
#pragma unroll
        for (int grp = 0; grp < 2; grp++) {
            const int off = ((grp ^ kap) * 16) + tig * 4;
            uint2 fa[4][2];
#pragma unroll
            for (int mi = 0; mi < 4; mi++) {
                const int r = wm + mi * 16 + gid;
                fa[mi][0] = *(const uint2*)(Ah + r * 32 + off);
                fa[mi][1] = *(const uint2*)(Ah + (r + 8) * 32 + off);
            }
            uint2 fb[4];
#pragma unroll
            for (int ni = 0; ni < 4; ni++)
                fb[ni] = *(const uint2*)(Bh + (wn + ni * 8 + gid) * 32 + off);
#pragma unroll
            for (int mi = 0; mi < 4; mi++)
#pragma unroll
                for (int ni = 0; ni < 4; ni++)
                    mma16h(acc[mi][ni],
                           fa[mi][0].x, fa[mi][1].x, fa[mi][0].y, fa[mi][1].y,
                           fb[ni].x, fb[ni].y);
        }
    }

    // epilogue
#pragma unroll
    for (int ni = 0; ni < 4; ni++) {
        const int cb = bn + wn + ni * 8;
        const int c0 = 2 * tig, c1 = 2 * tig + 1;
        const float b0 = bias[cb + c0], b1 = bias[cb + c1];
#pragma unroll
        for (int mi = 0; mi < 4; mi++) {
            const int row = bm + wm + mi * 16 + gid;
#pragma unroll
            for (int rr = 0; rr < 2; rr++) {
                const int r = row + rr * 8;
                float v0 = acc[mi][ni][rr * 2 + 0] + b0;
                float v1 = acc[mi][ni][rr * 2 + 1] + b1;
                size_t off = (size_t)r * N + cb + c0;
                if (RES) { v0 += res[off]; v1 += res[off + 1]; }
                if (RELU) { v0 = fmaxf(v0, 0.f); v1 = fmaxf(v1, 0.f); }
                if (OUT == 0) {
                    float2 o; o.x = v0; o.y = v1;
                    *(float2*)&((float*)Cv)[off] = o;
                } else if (OUT == 1) {
                    __half* C16 = (__half*)Cv;
                    int col0 = cb + c0;
                    size_t idx = (size_t)r * N + (col0 & ~15) + p16(col0 & 15);
                    *(__half2*)&C16[idx] = __floats2half2_rn(v0, v1);
                } else {
                    int col0 = cb + c0;
                    __half h0 = __float2half_rn(v0), h1v = __float2half_rn(v1);
                    if (col0 < 2048) {
                        size_t idx = (size_t)r * 2048 + (col0 & ~15) + p16(col0 & 15);
                        *(__half2*)&QKo[idx] = __halves2half2(h0, h1v);
                    } else {
                        int d0 = col0 - 2048;
                        int hd = d0 >> 6, dh = d0 & 63;
                        int b_ = r >> 11, l = r & 2047;
                        size_t lidx = (size_t)(l & ~15) + p16(l & 15);
                        size_t rowb = ((size_t)(b_ * HH + hd) * DHD + dh) * LL;
                        VTo[rowb + lidx]      = h0;
                        VTo[rowb + LL + lidx] = h1v;   // dh+1 (dh even)
                    }
                }
            }
        }
    }
}

// ============================================================
// FP16 tensor-core causal flash attention. (unchanged from R11)
// ============================================================
#define AQ 128

__global__ void __launch_bounds__(256) attn_h(
    const __half* __restrict__ qk, const __half* __restrict__ vt,
    __half* __restrict__ O)
{
    __shared__ __half Qs[128 * 64];
    __shared__ __half Ks[2][32 * 64];
    __shared__ __half Vts[2][64 * 32];
    __shared__ __half Ps[128 * 32];

    const int qi = blockIdx.x, h = blockIdx.y, b = blockIdx.z;
    const int tid = threadIdx.x, lane = tid & 31, wid = tid >> 5;
    const int gid = lane >> 2, tig = lane & 3;

    const uint32_t sQ = (uint32_t)__cvta_generic_to_shared(Qs);
    const uint32_t sK = (uint32_t)__cvta_generic_to_shared(Ks);
    const uint32_t sV = (uint32_t)__cvta_generic_to_shared(Vts);

    const __half* qbQ = qk + ((size_t)(b * LL + qi * AQ)) * 2048 + h * 64;
    const __half* qbK = qk + ((size_t)(b * LL)) * 2048 + 1024 + h * 64;
    const __half* vb  = vt + ((size_t)(b * HH + h) * DHD) * LL;

#pragma unroll
    for (int i = 0; i < 4; i++) {
        int c = tid + i * 256;
        int r = c >> 3, ch = c & 7;
        uint32_t dst = sQ + (uint32_t)(r * 128 + (((ch >> 1) ^ (r & 3)) * 32) + (ch & 1) * 16);
        cp_async16(dst, qbQ + (size_t)r * 2048 + ch * 8);
    }
    auto load_kv = [&](int kt, int slot) {
        {
            int r = tid >> 3, ch = tid & 7;
            uint32_t dst = sK + (uint32_t)(slot * 4096 + r * 128 + (((ch >> 1) ^ (r & 3)) * 32) + (ch & 1) * 16);
            cp_async16(dst, qbK + (size_t)(kt * 32 + r) * 2048 + ch * 8);
        }
        {
            int d = tid >> 2, ch = tid & 3;
            uint32_t dst = sV + (uint32_t)(slot * 4096 + d * 64 + (((ch >> 1) ^ ((d >> 1) & 1)) * 32) + (ch & 1) * 16);
            cp_async16(dst, vb + (size_t)d * LL + kt * 32 + ch * 8);
        }
    };
    load_kv(0, 0); cp_commit();

    float m0 = -1e30f, m1 = -1e30f, l0 = 0.f, l1 = 0.f;
    float oacc[8][4];
#pragma unroll
    for (int ni = 0; ni < 8; ni++)
#pragma unroll
        for (int c = 0; c < 4; c++) oacc[ni][c] = 0.f;

    const int r0 = 16 * wid + gid;
    const int rowg0 = qi * AQ + r0, rowg1 = rowg0 + 8;
    const int keyQ = r0 & 3;
    const int keyP = (r0 >> 1) & 1;
    const int ktmax = 4 * qi + 3;

    for (int kt = 0; kt <= ktmax; kt++) {
        cp_wait<0>();
        __syncthreads();
        if (kt + 1 <= ktmax) load_kv(kt + 1, (kt + 1) & 1);
        cp_commit();

        const __half* Kt  = Ks[kt & 1];
        const __half* Vtt = Vts[kt & 1];

        float sfr[4][4];
#pragma unroll
        for (int ni = 0; ni < 4; ni++)
#pragma unroll
            for (int c = 0; c < 4; c++) sfr[ni][c] = 0.f;
#pragma unroll
        for (int grp = 0; grp < 4; grp++) {
            const __half* qa = Qs + r0 * 64 + ((grp ^ keyQ) * 16) + tig * 4;
            uint2 fa0 = *(const uint2*)qa;
            uint2 fa1 = *(const uint2*)(qa + 8 * 64);
#pragma unroll
            for (int ni = 0; ni < 4; ni++) {
                int kk = 8 * ni + gid;
                uint2 fb = *(const uint2*)(Kt + kk * 64 + ((grp ^ (kk & 3)) * 16) + tig * 4);
                mma16h(sfr[ni], fa0.x, fa1.x, fa0.y, fa1.y, fb.x, fb.y);
            }
        }

        const bool domask = (kt >= 4 * qi);
        const int colbase = kt * 32;
        float p[4][4];
#pragma unroll
        for (int ni = 0; ni < 4; ni++)
#pragma unroll
            for (int c = 0; c < 4; c++) {
                float v = sfr[ni][c] * 0.125f;
                if (domask) {
                    int col = colbase + 8 * ni + 2 * tig + (c & 1);
                    int rg = (c < 2) ? rowg0 : rowg1;
                    if (col > rg) v = -1e30f;
                }
                p[ni][c] = v;
            }
#pragma unroll
        for (int half = 0; half < 2; half++) {
            float rmax = -1e30f;
#pragma unroll
            for (int ni = 0; ni < 4; ni++) {
                rmax = fmaxf(rmax, p[ni][half * 2]);
                rmax = fmaxf(rmax, p[ni][half * 2 + 1]);
            }
            rmax = fmaxf(rmax, __shfl_xor_sync(0xffffffffu, rmax, 1));
            rmax = fmaxf(rmax, __shfl_xor_sync(0xffffffffu, rmax, 2));
            float mprev = half ? m1 : m0;
            float mn = fmaxf(mprev, rmax);
            float alpha = __expf(mprev - mn);
            float psum = 0.f;
#pragma unroll
            for (int ni = 0; ni < 4; ni++) {
#pragma unroll
                for (int j = 0; j < 2; j++) {
                    float e = __expf(p[ni][half * 2 + j] - mn);
                    p[ni][half * 2 + j] = e;
                    psum += e;
                }
            }
            psum += __shfl_xor_sync(0xffffffffu, psum, 1);
            psum += __shfl_xor_sync(0xffffffffu, psum, 2);
            if (half == 0) { l0 = l0 * alpha + psum; m0 = mn; }
            else           { l1 = l1 * alpha + psum; m1 = mn; }
#pragma unroll
            for (int ni = 0; ni < 8; ni++) {
                oacc[ni][half * 2]     *= alpha;
                oacc[ni][half * 2 + 1] *= alpha;
            }
        }

#pragma unroll
        for (int ni = 0; ni < 4; ni++) {
            int g16 = ni >> 1;
            int off0 = r0 * 32 + ((g16 ^ keyP) * 16) + 4 * tig + 2 * (ni & 1);
            *(__half2*)(Ps + off0)          = __floats2half2_rn(p[ni][0], p[ni][1]);
            *(__half2*)(Ps + off0 + 8 * 32) = __floats2half2_rn(p[ni][2], p[ni][3]);
        }
        __syncwarp();

#pragma unroll
        for (int grp = 0; grp < 2; grp++) {
            const __half* pa = Ps + r0 * 32 + ((grp ^ keyP) * 16) + tig * 4;
            uint2 fa0 = *(const uint2*)pa;
            uint2 fa1 = *(const uint2*)(pa + 8 * 32);
#pragma unroll
            for (int ni = 0; ni < 8; ni++) {
                int dd = 8 * ni + gid;
                uint2 fb = *(const uint2*)(Vtt + dd * 32 + ((grp ^ ((dd >> 1) & 1)) * 16) + tig * 4);
                mma16h(oacc[ni], fa0.x, fa1.x, fa0.y, fa1.y, fb.x, fb.y);
            }
        }
    }

    float inv0 = 1.0f / l0, inv1 = 1.0f / l1;
    size_t ob0 = ((size_t)(b * LL + rowg0) * HH + h) * DHD;
    size_t ob1 = ((size_t)(b * LL + rowg1) * HH + h) * DHD;
#pragma unroll
    for (int ni = 0; ni < 8; ni++) {
        int dcol = 8 * ni + 2 * tig;
        int pos = (dcol & ~15) + p16(dcol & 15);
        *(__half2*)&O[ob0 + pos] = __floats2half2_rn(oacc[ni][0] * inv0, oacc[ni][1] * inv0);
        *(__half2*)&O[ob1 + pos] = __floats2half2_rn(oacc[ni][2] * inv1, oacc[ni][3] * inv1);
    }
}

// ============================================================
// LayerNorm (ddof=1, (std+eps)); optional fp16-permuted 2nd output
// ============================================================
__global__ void __launch_bounds__(256) ln_kernel(
    const float* __restrict__ X, const float* __restrict__ gamma,
    const float* __restrict__ beta, float* __restrict__ Y,
    __half* __restrict__ Yr)
{
    const int row = blockIdx.x;
    const int tid = threadIdx.x;
    const int lane = tid & 31, wid = tid >> 5;
    __shared__ float red[8];

    float4 v = *(const float4*)&X[(size_t)row * DD + tid * 4];

    float s = v.x + v.y + v.z + v.w;
#pragma unroll
    for (int off = 16; off > 0; off >>= 1) s += __shfl_xor_sync(0xffffffffu, s, off);
    if (lane == 0) red[wid] = s;
    __syncthreads();
    float mean = 0.f;
#pragma unroll
    for (int i = 0; i < 8; i++) mean += red[i];
    mean *= (1.0f / 1024.f);
    __syncthreads();

    float dx = v.x - mean, dy = v.y - mean, dz = v.z - mean, dw = v.w - mean;
    float ss = dx*dx + dy*dy + dz*dz + dw*dw;
#pragma unroll
    for (int off = 16; off > 0; off >>= 1) ss += __shfl_xor_sync(0xffffffffu, ss, off);
    if (lane == 0) red[wid] = ss;
    __syncthreads();
    float var = 0.f;
#pragma unroll
    for (int i = 0; i < 8; i++) var += red[i];
    var *= (1.0f / 1023.f);
    float istd = 1.0f / (sqrtf(var) + 1e-6f);

    float4 g  = *(const float4*)&gamma[tid * 4];
    float4 bb = *(const float4*)&beta[tid * 4];
    float o[4];
    o[0] = dx * istd * g.x + bb.x;
    o[1] = dy * istd * g.y + bb.y;
    o[2] = dz * istd * g.z + bb.z;
    o[3] = dw * istd * g.w + bb.w;
    float4 outv; outv.x = o[0]; outv.y = o[1]; outv.z = o[2]; outv.w = o[3];
    *(float4*)&Y[(size_t)row * DD + tid * 4] = outv;
    if (Yr) {
        __half* yr = Yr + (size_t)row * DD;
#pragma unroll
        for (int e = 0; e < 4; e++) {
            int col = tid * 4 + e;
            yr[(col & ~15) + p16(col & 15)] = __float2half_rn(o[e]);
        }
    }
}

// ============================================================
extern "C" void kernel_launch(void* const* d_in, const int* in_sizes, int n_in,
                              void* d_out, int out_size)
{
    const float* x     = (const float*)d_in[0];
    const float* Wqkv  = (const float*)d_in[2];
    const float* bqkv  = (const float*)d_in[3];
    const float* Wo    = (const float*)d_in[4];
    const float* bo    = (const float*)d_in[5];
    const float* ln1_a = (const float*)d_in[6];
    const float* ln1_b = (const float*)d_in[7];
    const float* W1    = (const float*)d_in[8];
    const float* b1    = (const float*)d_in[9];
    const float* W2    = (const float*)d_in[10];
    const float* b2    = (const float*)d_in[11];
    const float* ln2_a = (const float*)d_in[12];
    const float* ln2_b = (const float*)d_in[13];
    float* out = (float*)d_out;

    float  *t0, *h1;
    __half *qkb, *vtb, *attn, *h1r, *ffn, *xr, *wqkvr, *wor, *w1r, *w2r;
    cudaGetSymbolAddress((void**)&qkb,   g_qk);
    cudaGetSymbolAddress((void**)&vtb,   g_vt);
    cudaGetSymbolAddress((void**)&attn,  g_attn);
    cudaGetSymbolAddress((void**)&t0,    g_t0);
    cudaGetSymbolAddress((void**)&h1,    g_h1);
    cudaGetSymbolAddress((void**)&h1r,   g_h1r);
    cudaGetSymbolAddress((void**)&ffn,   g_ffn);
    cudaGetSymbolAddress((void**)&xr,    g_xr);
    cudaGetSymbolAddress((void**)&wqkvr, g_wqkvr);
    cudaGetSymbolAddress((void**)&wor,   g_wor);
    cudaGetSymbolAddress((void**)&w1r,   g_w1r);
    cudaGetSymbolAddress((void**)&w2r,   g_w2r);

    cudaFuncSetAttribute(gemm_h<false,false,2>, cudaFuncAttributeMaxDynamicSharedMemorySize, GEMM_SMEM);
    cudaFuncSetAttribute(gemm_h<false,true ,0>, cudaFuncAttributeMaxDynamicSharedMemorySize, GEMM_SMEM);
    cudaFuncSetAttribute(gemm_h<true ,false,1>, cudaFuncAttributeMaxDynamicSharedMemorySize, GEMM_SMEM);

    dim3 blk(256);

    // convert+permute all GEMM A/B operands to fp16 16-groups
    round_perm16<<<(MTOT*DD/16 + 511)/512, blk>>>(x, xr, MTOT*DD/16);
    round_perm16<<<(3*DD*DD/16 + 511)/512, blk>>>(Wqkv, wqkvr, 3*DD*DD/16);
    round_perm16<<<(DD*DD/16 + 511)/512, blk>>>(Wo, wor, DD*DD/16);
    round_perm16<<<(DFFN*DD/16 + 511)/512, blk>>>(W1, w1r, DFFN*DD/16);
    round_perm16<<<(DD*DFFN/16 + 511)/512, blk>>>(W2, w2r, DD*DFFN/16);

    // 1) QKV GEMM: Q/K -> g_qk (fp16 perm16), V -> g_vt (fp16 transposed)
    gemm_h<false,false,2><<<dim3(3072/128, MTOT/128), blk, GEMM_SMEM>>>(
        xr, wqkvr, bqkv, nullptr, nullptr, qkb, vtb, MTOT, 3*DD, DD);

    // 2) fp16 tensor-core causal flash attention -> attn (fp16 perm16)
    attn_h<<<dim3(LL/AQ, HH, BBAT), blk>>>(qkb, vtb, attn);

    // 3) t0 = attn @ Wo^T + bo + x (fp32 out)
    gemm_h<false,true,0><<<dim3(DD/128, MTOT/128), blk, GEMM_SMEM>>>(
        attn, wor, bo, x, t0, nullptr, nullptr, MTOT, DD, DD);

    // 4) h1 = LN1(t0) fp32, h1r fp16 perm16
    ln_kernel<<<MTOT, blk>>>(t0, ln1_a, ln1_b, h1, h1r);

    // 5) ffn = relu(h1r @ W1^T + b1) (fp16 perm16 out)
    gemm_h<true,false,1><<<dim3(DFFN/128, MTOT/128), blk, GEMM_SMEM>>>(
        h1r, w1r, b1, nullptr, ffn, nullptr, nullptr, MTOT, DFFN, DD);

    // 6) t0 = ffn @ W2^T + b2 + h1 (fp32 out)
    gemm_h<false,true,0><<<dim3(DD/128, MTOT/128), blk, GEMM_SMEM>>>(
        ffn, w2r, b2, h1, t0, nullptr, nullptr, MTOT, DD, DFFN);

    // 7) out = LN2(t0)
    ln_kernel<<<MTOT, blk>>>(t0, ln2_a, ln2_b, out, nullptr);
}

// round 16
// speedup vs baseline: 1.5157x; 1.0074x over previous
#include <cuda_runtime.h>
#include <cuda_fp16.h>
#include <cstdint>
#include <math.h>

#define BBAT 2
#define LL   2048
#define DD   1024
#define HH   16
#define DHD  64
#define DFFN 4096
#define MTOT (BBAT*LL)   // 4096

// ---- scratch (__device__ globals; no allocation allowed) ----
__device__ __half g_qk  [(size_t)MTOT*2*DD];          // Q|K fp16 perm16
__device__ __half g_vt  [(size_t)BBAT*HH*DHD*LL];     // V^T fp16 perm16(l)
__device__ __half g_attn[(size_t)MTOT*DD];
__device__ float  g_t0  [(size_t)MTOT*DD];
__device__ float  g_h1  [(size_t)MTOT*DD];
__device__ __half g_h1r [(size_t)MTOT*DD];
__device__ __half g_ffn [(size_t)MTOT*DFFN];
__device__ __half g_xr  [(size_t)MTOT*DD];
__device__ __half g_wqkvr[(size_t)3*DD*DD];
__device__ __half g_wor [(size_t)DD*DD];
__device__ __half g_w1r [(size_t)DFFN*DD];
__device__ __half g_w2r [(size_t)DD*DFFN];

// ============================================================
// Helpers
// ============================================================
__device__ __forceinline__ void mma16h(float* c, uint32_t a0, uint32_t a1,
                                       uint32_t a2, uint32_t a3,
                                       uint32_t b0, uint32_t b1) {
    asm volatile(
        "mma.sync.aligned.m16n8k16.row.col.f32.f16.f16.f32 "
        "{%0,%1,%2,%3}, {%4,%5,%6,%7}, {%8,%9}, {%0,%1,%2,%3};\n"
        : "+f"(c[0]), "+f"(c[1]), "+f"(c[2]), "+f"(c[3])
        : "r"(a0), "r"(a1), "r"(a2), "r"(a3), "r"(b0), "r"(b1));
}
__device__ __forceinline__ void cp_async16(uint32_t dst, const void* src) {
    asm volatile("cp.async.cg.shared.global [%0], [%1], 16;\n" :: "r"(dst), "l"(src));
}
__device__ __forceinline__ void cp_commit() { asm volatile("cp.async.commit_group;\n"); }
template<int N> __device__ __forceinline__ void cp_wait() {
    asm volatile("cp.async.wait_group %0;\n" :: "n"(N));
}
// fp16 16-group permuted index: order [0,1,8,9,2,3,10,11,4,5,12,13,6,7,14,15]
__device__ __forceinline__ int p16(int c) {
    return ((c & 7) >> 1) * 4 + ((c >> 3) & 1) * 2 + (c & 1);
}
__device__ __forceinline__ uint32_t h2u(__half2 h) {
    return *reinterpret_cast<uint32_t*>(&h);
}

// ============================================================
// Fused fp32 -> fp16 convert+permute for all 5 operand tensors.
// Total 16-groups: x 262144 | Wqkv 196608 | Wo 65536 | W1 262144 | W2 262144
// = 1048576 exactly. 2 groups per thread.
// ============================================================
#define CONV_TOTAL 1048576

__global__ void __launch_bounds__(256) fused_conv(
    const float* __restrict__ x,    __half* __restrict__ xr,
    const float* __restrict__ wqkv, __half* __restrict__ wqkvr,
    const float* __restrict__ wo,   __half* __restrict__ wor,
    const float* __restrict__ w1,   __half* __restrict__ w1r,
    const float* __restrict__ w2,   __half* __restrict__ w2r)
{
    int i0 = blockIdx.x * 512 + threadIdx.x;
#pragma unroll
    for (int k = 0; k < 2; k++) {
        int i = i0 + k * 256;
        const float* src; __half* dst; int off;
        if (i < 262144)      { src = x;    dst = xr;    off = i; }
        else if (i < 458752) { src = wqkv; dst = wqkvr; off = i - 262144; }
        else if (i < 524288) { src = wo;   dst = wor;   off = i - 458752; }
        else if (i < 786432) { src = w1;   dst = w1r;   off = i - 524288; }
        else                 { src = w2;   dst = w2r;   off = i - 786432; }
        const float4* s4 = (const float4*)(src + (size_t)off * 16);
        float4 v0 = s4[0], v1 = s4[1], v2 = s4[2], v3 = s4[3];
        uint4 o0, o1;
        o0.x = h2u(__floats2half2_rn(v0.x, v0.y));
        o0.y = h2u(__floats2half2_rn(v2.x, v2.y));
        o0.z = h2u(__floats2half2_rn(v0.z, v0.w));
        o0.w = h2u(__floats2half2_rn(v2.z, v2.w));
        o1.x = h2u(__floats2half2_rn(v1.x, v1.y));
        o1.y = h2u(__floats2half2_rn(v3.x, v3.y));
        o1.z = h2u(__floats2half2_rn(v1.z, v1.w));
        o1.w = h2u(__floats2half2_rn(v3.z, v3.w));
        uint4* d4 = (uint4*)(dst + (size_t)off * 16);
        d4[0] = o0; d4[1] = o1;
    }
}

// ============================================================
// FP16 mma GEMM on pre-permuted operands. (R15 config unchanged)
// OUT: 0 = fp32, 1 = fp16 perm16, 2 = QKV split (Q/K perm16 + V^T)
// ============================================================
#define BK 32
#define NSLOT 4
#define STAGE_B 16384
#define GEMM_SMEM (NSLOT * STAGE_B)        // 65536

template<bool RELU, bool RES, int OUT>
__global__ void __launch_bounds__(256, 2) gemm_h(
    const __half* __restrict__ A, const __half* __restrict__ W,
    const float* __restrict__ bias, const float* __restrict__ res,
    void* __restrict__ Cv, __half* __restrict__ QKo, __half* __restrict__ VTo,
    int M, int N, int K)
{
    extern __shared__ char smem[];
    const uint32_t sbase = (uint32_t)__cvta_generic_to_shared(smem);

    const int tid = threadIdx.x;
    const int lane = tid & 31, wid = tid >> 5;
    const int bm = blockIdx.y * 128, bn = blockIdx.x * 128;
    const int wm = (wid >> 2) * 64;
    const int wn = (wid & 3) * 32;
    const int gid = lane >> 2, tig = lane & 3;
    const int kap = (gid >> 1) & 1;
    const int T = K / BK;

    float acc[4][4][4];
#pragma unroll
    for (int mi = 0; mi < 4; mi++)
#pragma unroll
        for (int ni = 0; ni < 4; ni++)
#pragma unroll
            for (int r = 0; r < 4; r++) acc[mi][ni][r] = 0.f;

    auto load_tile = [&](int t, int slot) {
        const uint32_t st = sbase + (uint32_t)slot * STAGE_B;
        const int kt = t * BK;
#pragma unroll
        for (int i = 0; i < 2; i++) {
            int c = tid + i * 256;
            int r = c >> 2, h = c & 3, g = h >> 1;
            uint32_t dst = st + (uint32_t)(r * 64 + ((g ^ ((r >> 1) & 1)) * 32) + (h & 1) * 16);
            cp_async16(dst, A + (size_t)(bm + r) * K + kt + h * 8);
        }
        const uint32_t stb = st + 8192;
#pragma unroll
        for (int i = 0; i < 2; i++) {
            int c = tid + i * 256;
            int r = c >> 2, h = c & 3, g = h >> 1;
            uint32_t dst = stb + (uint32_t)(r * 64 + ((g ^ ((r >> 1) & 1)) * 32) + (h & 1) * 16);
            cp_async16(dst, W + (size_t)(bn + r) * K + kt + h * 8);
        }
    };

    load_tile(0, 0); cp_commit();
    load_tile(1, 1); cp_commit();
    load_tile(2, 2); cp_commit();

    for (int t = 0; t < T; t++) {
        cp_wait<2>();
        __syncthreads();     // single barrier per tile
        if (t + 3 < T) load_tile(t + 3, (t + 3) & 3);
        cp_commit();

        const __half* Ah = (const __half*)(smem + (size_t)(t & 3) * STAGE_B);
        const __half* Bh = Ah + 128 * 32;
#pragma unroll
        for (int grp = 0; grp < 2; grp++) {
            const int off = ((grp ^ kap) * 16) + tig * 4;
            uint2 fa[4][2];
#pragma unroll
            for (int mi = 0; mi < 4; mi++) {
                const int r = wm + mi * 16 + gid;
                fa[mi][0] = *(const uint2*)(Ah + r * 32 + off);
                fa[mi][1] = *(const uint2*)(Ah + (r + 8) * 32 + off);
            }
            uint2 fb[4];
#pragma unroll
            for (int ni = 0; ni < 4; ni++)
                fb[ni] = *(const uint2*)(Bh + (wn + ni * 8 + gid) * 32 + off);
#pragma unroll
            for (int mi = 0; mi < 4; mi++)
#pragma unroll
                for (int ni = 0; ni < 4; ni++)
                    mma16h(acc[mi][ni],
                           fa[mi][0].x, fa[mi][1].x, fa[mi][0].y, fa[mi][1].y,
                           fb[ni].x, fb[ni].y);
        }
    }

    // epilogue
#pragma unroll
    for (int ni = 0; ni < 4; ni++) {
        const int cb = bn + wn + ni * 8;
        const int c0 = 2 * tig, c1 = 2 * tig + 1;
        const float b0 = bias[cb + c0], b1 = bias[cb + c1];
#pragma unroll
        for (int mi = 0; mi < 4; mi++) {
            const int row = bm + wm + mi * 16 + gid;
#pragma unroll
            for (int rr = 0; rr < 2; rr++) {
                const int r = row + rr * 8;
                float v0 = acc[mi][ni][rr * 2 + 0] + b0;
                float v1 = acc[mi][ni][rr * 2 + 1] + b1;
                size_t off = (size_t)r * N + cb + c0;
                if (RES) { v0 += res[off]; v1 += res[off + 1]; }
                if (RELU) { v0 = fmaxf(v0, 0.f); v1 = fmaxf(v1, 0.f); }
                if (OUT == 0) {
                    float2 o; o.x = v0; o.y = v1;
                    *(float2*)&((float*)Cv)[off] = o;
                } else if (OUT == 1) {
                    __half* C16 = (__half*)Cv;
                    int col0 = cb + c0;
                    size_t idx = (size_t)r * N + (col0 & ~15) + p16(col0 & 15);
                    *(__half2*)&C16[idx] = __floats2half2_rn(v0, v1);
                } else {
                    int col0 = cb + c0;
                    __half h0 = __float2half_rn(v0), h1v = __float2half_rn(v1);
                    if (col0 < 2048) {
                        size_t idx = (size_t)r * 2048 + (col0 & ~15) + p16(col0 & 15);
                        *(__half2*)&QKo[idx] = __halves2half2(h0, h1v);
                    } else {
                        int d0 = col0 - 2048;
                        int hd = d0 >> 6, dh = d0 & 63;
                        int b_ = r >> 11, l = r & 2047;
                        size_t lidx = (size_t)(l & ~15) + p16(l & 15);
                        size_t rowb = ((size_t)(b_ * HH + hd) * DHD + dh) * LL;
                        VTo[rowb + lidx]      = h0;
                        VTo[rowb + LL + lidx] = h1v;   // dh+1 (dh even)
                    }
                }
            }
        }
    }
}

// ============================================================
// FP16 tensor-core causal flash attention.
// Heavy-first block order (qi reversed); Q fragments hoisted to regs.
// ============================================================
#define AQ 128

__global__ void __launch_bounds__(256) attn_h(
    const __half* __restrict__ qk, const __half* __restrict__ vt,
    __half* __restrict__ O)
{
    __shared__ __half Qs[128 * 64];
    __shared__ __half Ks[2][32 * 64];
    __shared__ __half Vts[2][64 * 32];
    __shared__ __half Ps[128 * 32];

    const int qi = (int)gridDim.x - 1 - (int)blockIdx.x;   // heavy-first
    const int h = blockIdx.y, b = blockIdx.z;
    const int tid = threadIdx.x, lane = tid & 31, wid = tid >> 5;
    const int gid = lane >> 2, tig = lane & 3;

    const uint32_t sQ = (uint32_t)__cvta_generic_to_shared(Qs);
    const uint32_t sK = (uint32_t)__cvta_generic_to_shared(Ks);
    const uint32_t sV = (uint32_t)__cvta_generic_to_shared(Vts);

    const __half* qbQ = qk + ((size_t)(b * LL + qi * AQ)) * 2048 + h * 64;
    const __half* qbK = qk + ((size_t)(b * LL)) * 2048 + 1024 + h * 64;
    const __half* vb  = vt + ((size_t)(b * HH + h) * DHD) * LL;

    // Q fill (group 0)
#pragma unroll
    for (int i = 0; i < 4; i++) {
        int c = tid + i * 256;
        int r = c >> 3, ch = c & 7;
        uint32_t dst = sQ + (uint32_t)(r * 128 + (((ch >> 1) ^ (r & 3)) * 32) + (ch & 1) * 16);
        cp_async16(dst, qbQ + (size_t)r * 2048 + ch * 8);
    }
    cp_commit();
    auto load_kv = [&](int kt, int slot) {
        {
            int r = tid >> 3, ch = tid & 7;
            uint32_t dst = sK + (uint32_t)(slot * 4096 + r * 128 + (((ch >> 1) ^ (r & 3)) * 32) + (ch & 1) * 16);
            cp_async16(dst, qbK + (size_t)(kt * 32 + r) * 2048 + ch * 8);
        }
        {
            int d = tid >> 2, ch = tid & 3;
            uint32_t dst = sV + (uint32_t)(slot * 4096 + d * 64 + (((ch >> 1) ^ ((d >> 1) & 1)) * 32) + (ch & 1) * 16);
            cp_async16(dst, vb + (size_t)d * LL + kt * 32 + ch * 8);
        }
    };
    load_kv(0, 0); cp_commit();

    float m0 = -1e30f, m1 = -1e30f, l0 = 0.f, l1 = 0.f;
    float oacc[8][4];
#pragma unroll
    for (int ni = 0; ni < 8; ni++)
#pragma unroll
        for (int c = 0; c < 4; c++) oacc[ni][c] = 0.f;

    const int r0 = 16 * wid + gid;
    const int rowg0 = qi * AQ + r0, rowg1 = rowg0 + 8;
    const int keyQ = r0 & 3;
    const int keyP = (r0 >> 1) & 1;
    const int ktmax = 4 * qi + 3;

    // hoist loop-invariant Q fragments into registers
    cp_wait<1>();            // Q group complete (KV may still be in flight)
    __syncthreads();
    uint2 qfa[4][2];
#pragma unroll
    for (int grp = 0; grp < 4; grp++) {
        const __half* qa = Qs + r0 * 64 + ((grp ^ keyQ) * 16) + tig * 4;
        qfa[grp][0] = *(const uint2*)qa;
        qfa[grp][1] = *(const uint2*)(qa + 8 * 64);
    }

    for (int kt = 0; kt <= ktmax; kt++) {
        cp_wait<0>();
        __syncthreads();
        if (kt + 1 <= ktmax) load_kv(kt + 1, (kt + 1) & 1);
        cp_commit();

        const __half* Kt  = Ks[kt & 1];
        const __half* Vtt = Vts[kt & 1];

        float sfr[4][4];
#pragma unroll
        for (int ni = 0; ni < 4; ni++)
#pragma unroll
            for (int c = 0; c < 4; c++) sfr[ni][c] = 0.f;
#pragma unroll
        for (int grp = 0; grp < 4; grp++) {
#pragma unroll
            for (int ni = 0; ni < 4; ni++) {
                int kk = 8 * ni + gid;
                uint2 fb = *(const uint2*)(Kt + kk * 64 + ((grp ^ (kk & 3)) * 16) + tig * 4);
                mma16h(sfr[ni], qfa[grp][0].x, qfa[grp][1].x,
                       qfa[grp][0].y, qfa[grp][1].y, fb.x, fb.y);
            }
        }

        const bool domask = (kt >= 4 * qi);
        const int colbase = kt * 32;
        float p[4][4];
#pragma unroll
        for (int ni = 0; ni < 4; ni++)
#pragma unroll
            for (int c = 0; c < 4; c++) {
                float v = sfr[ni][c] * 0.125f;
                if (domask) {
                    int col = colbase + 8 * ni + 2 * tig + (c & 1);
                    int rg = (c < 2) ? rowg0 : rowg1;
                    if (col > rg) v = -1e30f;
                }
                p[ni][c] = v;
            }
#pragma unroll
        for (int half = 0; half < 2; half++) {
            float rmax = -1e30f;
#pragma unroll
            for (int ni = 0; ni < 4; ni++) {
                rmax = fmaxf(rmax, p[ni][half * 2]);
                rmax = fmaxf(rmax, p[ni][half * 2 + 1]);
            }
            rmax = fmaxf(rmax, __shfl_xor_sync(0xffffffffu, rmax, 1));
            rmax = fmaxf(rmax, __shfl_xor_sync(0xffffffffu, rmax, 2));
            float mprev = half ? m1 : m0;
            float mn = fmaxf(mprev, rmax);
            float alpha = __expf(mprev - mn);
            float psum = 0.f;
#pragma unroll
            for (int ni = 0; ni < 4; ni++) {
#pragma unroll
                for (int j = 0; j < 2; j++) {
                    float e = __expf(p[ni][half * 2 + j] - mn);
                    p[ni][half * 2 + j] = e;
                    psum += e;
                }
            }
            psum += __shfl_xor_sync(0xffffffffu, psum, 1);
            psum += __shfl_xor_sync(0xffffffffu, psum, 2);
            if (half == 0) { l0 = l0 * alpha + psum; m0 = mn; }
            else           { l1 = l1 * alpha + psum; m1 = mn; }
#pragma unroll
            for (int ni = 0; ni < 8; ni++) {
                oacc[ni][half * 2]     *= alpha;
                oacc[ni][half * 2 + 1] *= alpha;
            }
        }

#pragma unroll
        for (int ni = 0; ni < 4; ni++) {
            int g16 = ni >> 1;
            int off0 = r0 * 32 + ((g16 ^ keyP) * 16) + 4 * tig + 2 * (ni & 1);
            *(__half2*)(Ps + off0)          = __floats2half2_rn(p[ni][0], p[ni][1]);
            *(__half2*)(Ps + off0 + 8 * 32) = __floats2half2_rn(p[ni][2], p[ni][3]);
        }
        __syncwarp();

#pragma unroll
        for (int grp = 0; grp < 2; grp++) {
            const __half* pa = Ps + r0 * 32 + ((grp ^ keyP) * 16) + tig * 4;
            uint2 fa0 = *(const uint2*)pa;
            uint2 fa1 = *(const uint2*)(pa + 8 * 32);
#pragma unroll
            for (int ni = 0; ni < 8; ni++) {
                int dd = 8 * ni + gid;
                uint2 fb = *(const uint2*)(Vtt + dd * 32 + ((grp ^ ((dd >> 1) & 1)) * 16) + tig * 4);
                mma16h(oacc[ni], fa0.x, fa1.x, fa0.y, fa1.y, fb.x, fb.y);
            }
        }
    }

    float inv0 = 1.0f / l0, inv1 = 1.0f / l1;
    size_t ob0 = ((size_t)(b * LL + rowg0) * HH + h) * DHD;
    size_t ob1 = ((size_t)(b * LL + rowg1) * HH + h) * DHD;
#pragma unroll
    for (int ni = 0; ni < 8; ni++) {
        int dcol = 8 * ni + 2 * tig;
        int pos = (dcol & ~15) + p16(dcol & 15);
        *(__half2*)&O[ob0 + pos] = __floats2half2_rn(oacc[ni][0] * inv0, oacc[ni][1] * inv0);
        *(__half2*)&O[ob1 + pos] = __floats2half2_rn(oacc[ni][2] * inv1, oacc[ni][3] * inv1);
    }
}

// ============================================================
// LayerNorm (ddof=1, (std+eps)); optional fp16-permuted 2nd output
// ============================================================
__global__ void __launch_bounds__(256) ln_kernel(
    const float* __restrict__ X, const float* __restrict__ gamma,
    const float* __restrict__ beta, float* __restrict__ Y,
    __half* __restrict__ Yr)
{
    const int row = blockIdx.x;
    const int tid = threadIdx.x;
    const int lane = tid & 31, wid = tid >> 5;
    __shared__ float red[8];

    float4 v = *(const float4*)&X[(size_t)row * DD + tid * 4];

    float s = v.x + v.y + v.z + v.w;
#pragma unroll
    for (int off = 16; off > 0; off >>= 1) s += __shfl_xor_sync(0xffffffffu, s, off);
    if (lane == 0) red[wid] = s;
    __syncthreads();
    float mean = 0.f;
#pragma unroll
    for (int i = 0; i < 8; i++) mean += red[i];
    mean *= (1.0f / 1024.f);
    __syncthreads();

    float dx = v.x - mean, dy = v.y - mean, dz = v.z - mean, dw = v.w - mean;
    float ss = dx*dx + dy*dy + dz*dz + dw*dw;
#pragma unroll
    for (int off = 16; off > 0; off >>= 1) ss += __shfl_xor_sync(0xffffffffu, ss, off);
    if (lane == 0) red[wid] = ss;
    __syncthreads();
    float var = 0.f;
#pragma unroll
    for (int i = 0; i < 8; i++) var += red[i];
    var *= (1.0f / 1023.f);
    float istd = 1.0f / (sqrtf(var) + 1e-6f);

    float4 g  = *(const float4*)&gamma[tid * 4];
    float4 bb = *(const float4*)&beta[tid * 4];
    float o[4];
    o[0] = dx * istd * g.x + bb.x;
    o[1] = dy * istd * g.y + bb.y;
    o[2] = dz * istd * g.z + bb.z;
    o[3] = dw * istd * g.w + bb.w;
    float4 outv; outv.x = o[0]; outv.y = o[1]; outv.z = o[2]; outv.w = o[3];
    *(float4*)&Y[(size_t)row * DD + tid * 4] = outv;
    if (Yr) {
        __half* yr = Yr + (size_t)row * DD;
#pragma unroll
        for (int e = 0; e < 4; e++) {
            int col = tid * 4 + e;
            yr[(col & ~15) + p16(col & 15)] = __float2half_rn(o[e]);
        }
    }
}

// ============================================================
extern "C" void kernel_launch(void* const* d_in, const int* in_sizes, int n_in,
                              void* d_out, int out_size)
{
    const float* x     = (const float*)d_in[0];
    const float* Wqkv  = (const float*)d_in[2];
    const float* bqkv  = (const float*)d_in[3];
    const float* Wo    = (const float*)d_in[4];
    const float* bo    = (const float*)d_in[5];
    const float* ln1_a = (const float*)d_in[6];
    const float* ln1_b = (const float*)d_in[7];
    const float* W1    = (const float*)d_in[8];
    const float* b1    = (const float*)d_in[9];
    const float* W2    = (const float*)d_in[10];
    const float* b2    = (const float*)d_in[11];
    const float* ln2_a = (const float*)d_in[12];
    const float* ln2_b = (const float*)d_in[13];
    float* out = (float*)d_out;

    float  *t0, *h1;
    __half *qkb, *vtb, *attn, *h1r, *ffn, *xr, *wqkvr, *wor, *w1r, *w2r;
    cudaGetSymbolAddress((void**)&qkb,   g_qk);
    cudaGetSymbolAddress((void**)&vtb,   g_vt);
    cudaGetSymbolAddress((void**)&attn,  g_attn);
    cudaGetSymbolAddress((void**)&t0,    g_t0);
    cudaGetSymbolAddress((void**)&h1,    g_h1);
    cudaGetSymbolAddress((void**)&h1r,   g_h1r);
    cudaGetSymbolAddress((void**)&ffn,   g_ffn);
    cudaGetSymbolAddress((void**)&xr,    g_xr);
    cudaGetSymbolAddress((void**)&wqkvr, g_wqkvr);
    cudaGetSymbolAddress((void**)&wor,   g_wor);
    cudaGetSymbolAddress((void**)&w1r,   g_w1r);
    cudaGetSymbolAddress((void**)&w2r,   g_w2r);

    cudaFuncSetAttribute(gemm_h<false,false,2>, cudaFuncAttributeMaxDynamicSharedMemorySize, GEMM_SMEM);
    cudaFuncSetAttribute(gemm_h<false,true ,0>, cudaFuncAttributeMaxDynamicSharedMemorySize, GEMM_SMEM);
    cudaFuncSetAttribute(gemm_h<true ,false,1>, cudaFuncAttributeMaxDynamicSharedMemorySize, GEMM_SMEM);

    dim3 blk(256);

    // 0) single fused convert+permute for all operands
    fused_conv<<<CONV_TOTAL / 512, blk>>>(x, xr, Wqkv, wqkvr, Wo, wor, W1, w1r, W2, w2r);

    // 1) QKV GEMM: Q/K -> g_qk (fp16 perm16), V -> g_vt (fp16 transposed)
    gemm_h<false,false,2><<<dim3(3072/128, MTOT/128), blk, GEMM_SMEM>>>(
        xr, wqkvr, bqkv, nullptr, nullptr, qkb, vtb, MTOT, 3*DD, DD);

    // 2) fp16 tensor-core causal flash attention -> attn (fp16 perm16)
    attn_h<<<dim3(LL/AQ, HH, BBAT), blk>>>(qkb, vtb, attn);

    // 3) t0 = attn @ Wo^T + bo + x (fp32 out)
    gemm_h<false,true,0><<<dim3(DD/128, MTOT/128), blk, GEMM_SMEM>>>(
        attn, wor, bo, x, t0, nullptr, nullptr, MTOT, DD, DD);

    // 4) h1 = LN1(t0) fp32, h1r fp16 perm16
    ln_kernel<<<MTOT, blk>>>(t0, ln1_a, ln1_b, h1, h1r);

    // 5) ffn = relu(h1r @ W1^T + b1) (fp16 perm16 out)
    gemm_h<true,false,1><<<dim3(DFFN/128, MTOT/128), blk, GEMM_SMEM>>>(
        h1r, w1r, b1, nullptr, ffn, nullptr, nullptr, MTOT, DFFN, DD);

    // 6) t0 = ffn @ W2^T + b2 + h1 (fp32 out)
    gemm_h<false,true,0><<<dim3(DD/128, MTOT/128), blk, GEMM_SMEM>>>(
        ffn, w2r, b2, h1, t0, nullptr, nullptr, MTOT, DD, DFFN);

    // 7) out = LN2(t0)
    ln_kernel<<<MTOT, blk>>>(t0, ln2_a, ln2_b, out, nullptr);
}

// round 17
// speedup vs baseline: 1.5399x; 1.0160x over previous
#include <cuda_runtime.h>
#include <cuda_fp16.h>
#include <cstdint>
#include <math.h>

#define BBAT 2
#define LL   2048
#define DD   1024
#define HH   16
#define DHD  64
#define DFFN 4096
#define MTOT (BBAT*LL)   // 4096

// ---- scratch (__device__ globals; no allocation allowed) ----
__device__ __half g_qk  [(size_t)MTOT*2*DD];          // Q|K fp16 perm16
__device__ __half g_vt  [(size_t)BBAT*HH*DHD*LL];     // V^T fp16 perm16(l)
__device__ __half g_attn[(size_t)MTOT*DD];
__device__ float  g_t0  [(size_t)MTOT*DD];
__device__ float  g_h1  [(size_t)MTOT*DD];
__device__ __half g_h1r [(size_t)MTOT*DD];
__device__ __half g_ffn [(size_t)MTOT*DFFN];
__device__ __half g_xr  [(size_t)MTOT*DD];
__device__ __half g_wqkvr[(size_t)3*DD*DD];
__device__ __half g_wor [(size_t)DD*DD];
__device__ __half g_w1r [(size_t)DFFN*DD];
__device__ __half g_w2r [(size_t)DD*DFFN];

// ============================================================
// Helpers
// ============================================================
__device__ __forceinline__ void mma16h(float* c, uint32_t a0, uint32_t a1,
                                       uint32_t a2, uint32_t a3,
                                       uint32_t b0, uint32_t b1) {
    asm volatile(
        "mma.sync.aligned.m16n8k16.row.col.f32.f16.f16.f32 "
        "{%0,%1,%2,%3}, {%4,%5,%6,%7}, {%8,%9}, {%0,%1,%2,%3};\n"
        : "+f"(c[0]), "+f"(c[1]), "+f"(c[2]), "+f"(c[3])
        : "r"(a0), "r"(a1), "r"(a2), "r"(a3), "r"(b0), "r"(b1));
}
__device__ __forceinline__ void cp_async16(uint32_t dst, const void* src) {
    asm volatile("cp.async.cg.shared.global [%0], [%1], 16;\n" :: "r"(dst), "l"(src));
}
__device__ __forceinline__ void cp_commit() { asm volatile("cp.async.commit_group;\n"); }
template<int N> __device__ __forceinline__ void cp_wait() {
    asm volatile("cp.async.wait_group %0;\n" :: "n"(N));
}
// fp16 16-group permuted index: order [0,1,8,9,2,3,10,11,4,5,12,13,6,7,14,15]
__device__ __forceinline__ int p16(int c) {
    return ((c & 7) >> 1) * 4 + ((c >> 3) & 1) * 2 + (c & 1);
}
__device__ __forceinline__ uint32_t h2u(__half2 h) {
    return *reinterpret_cast<uint32_t*>(&h);
}

// ============================================================
// Fused fp32 -> fp16 convert+permute for all 5 operand tensors.
// ============================================================
#define CONV_TOTAL 1048576

__global__ void __launch_bounds__(256) fused_conv(
    const float* __restrict__ x,    __half* __restrict__ xr,
    const float* __restrict__ wqkv, __half* __restrict__ wqkvr,
    const float* __restrict__ wo,   __half* __restrict__ wor,
    const float* __restrict__ w1,   __half* __restrict__ w1r,
    const float* __restrict__ w2,   __half* __restrict__ w2r)
{
    int i0 = blockIdx.x * 512 + threadIdx.x;
#pragma unroll
    for (int k = 0; k < 2; k++) {
        int i = i0 + k * 256;
        const float* src; __half* dst; int off;
        if (i < 262144)      { src = x;    dst = xr;    off = i; }
        else if (i < 458752) { src = wqkv; dst = wqkvr; off = i - 262144; }
        else if (i < 524288) { src = wo;   dst = wor;   off = i - 458752; }
        else if (i < 786432) { src = w1;   dst = w1r;   off = i - 524288; }
        else                 { src = w2;   dst = w2r;   off = i - 786432; }
        const float4* s4 = (const float4*)(src + (size_t)off * 16);
        float4 v0 = s4[0], v1 = s4[1], v2 = s4[2], v3 = s4[3];
        uint4 o0, o1;
        o0.x = h2u(__floats2half2_rn(v0.x, v0.y));
        o0.y = h2u(__floats2half2_rn(v2.x, v2.y));
        o0.z = h2u(__floats2half2_rn(v0.z, v0.w));
        o0.w = h2u(__floats2half2_rn(v2.z, v2.w));
        o1.x = h2u(__floats2half2_rn(v1.x, v1.y));
        o1.y = h2u(__floats2half2_rn(v3.x, v3.y));
        o1.z = h2u(__floats2half2_rn(v1.z, v1.w));
        o1.w = h2u(__floats2half2_rn(v3.z, v3.w));
        uint4* d4 = (uint4*)(dst + (size_t)off * 16);
        d4[0] = o0; d4[1] = o1;
    }
}

// ============================================================
// FP16 mma GEMM on pre-permuted operands.
// BK=64 stages (halve per-tile bubbles), 3-slot ring, lookahead 2.
// 256 threads (8 warps, 2x4), warp 64x32, 2 CTAs/SM.
// Smem rows 128B (64 halves); XOR-(r&3) 32B-group swizzle.
// OUT: 0 = fp32, 1 = fp16 perm16, 2 = QKV split (Q/K perm16 + V^T)
// ============================================================
#define BK 64
#define NSLOT 3
#define STAGE_B 32768                       // 256 rows * 128 B
#define GEMM_SMEM (NSLOT * STAGE_B)         // 98304

template<bool RELU, bool RES, int OUT>
__global__ void __launch_bounds__(256, 2) gemm_h(
    const __half* __restrict__ A, const __half* __restrict__ W,
    const float* __restrict__ bias, const float* __restrict__ res,
    void* __restrict__ Cv, __half* __restrict__ QKo, __half* __restrict__ VTo,
    int M, int N, int K)
{
    extern __shared__ char smem[];
    const uint32_t sbase = (uint32_t)__cvta_generic_to_shared(smem);

    const int tid = threadIdx.x;
    const int lane = tid & 31, wid = tid >> 5;
    const int bm = blockIdx.y * 128, bn = blockIdx.x * 128;
    const int wm = (wid >> 2) * 64;
    const int wn = (wid & 3) * 32;
    const int gid = lane >> 2, tig = lane & 3;
    const int key = gid & 3;                 // swizzle key (row&3 for this warp's rows)
    const int T = K / BK;

    float acc[4][4][4];
#pragma unroll
    for (int mi = 0; mi < 4; mi++)
#pragma unroll
        for (int ni = 0; ni < 4; ni++)
#pragma unroll
            for (int r = 0; r < 4; r++) acc[mi][ni][r] = 0.f;

    auto load_tile = [&](int t, int slot) {
        const uint32_t st = sbase + (uint32_t)slot * STAGE_B;
        const int kt = t * BK;
        // A: 128 rows x 8 chunks(16B) = 1024 chunks
#pragma unroll
        for (int i = 0; i < 4; i++) {
            int c = tid + i * 256;
            int r = c >> 3, ch = c & 7;
            uint32_t dst = st + (uint32_t)(r * 128 + (((ch >> 1) ^ (r & 3)) * 32) + (ch & 1) * 16);
            cp_async16(dst, A + (size_t)(bm + r) * K + kt + ch * 8);
        }
        const uint32_t stb = st + 16384;
#pragma unroll
        for (int i = 0; i < 4; i++) {
            int c = tid + i * 256;
            int r = c >> 3, ch = c & 7;
            uint32_t dst = stb + (uint32_t)(r * 128 + (((ch >> 1) ^ (r & 3)) * 32) + (ch & 1) * 16);
            cp_async16(dst, W + (size_t)(bn + r) * K + kt + ch * 8);
        }
    };

    load_tile(0, 0); cp_commit();
    load_tile(1, 1); cp_commit();

    int sl = 0, sl_ld = 2;
    for (int t = 0; t < T; t++) {
        cp_wait<1>();
        __syncthreads();     // single barrier per BK64 tile
        if (t + 2 < T) load_tile(t + 2, sl_ld);
        cp_commit();

        const __half* Ah = (const __half*)(smem + (size_t)sl * STAGE_B);
        const __half* Bh = Ah + 128 * 64;
#pragma unroll
        for (int grp = 0; grp < 4; grp++) {
            const int off = ((grp ^ key) * 16) + tig * 4;
            uint2 fa[4][2];
#pragma unroll
            for (int mi = 0; mi < 4; mi++) {
                const int r = wm + mi * 16 + gid;
                fa[mi][0] = *(const uint2*)(Ah + r * 64 + off);
                fa[mi][1] = *(const uint2*)(Ah + (r + 8) * 64 + off);
            }
            uint2 fb[4];
#pragma unroll
            for (int ni = 0; ni < 4; ni++)
                fb[ni] = *(const uint2*)(Bh + (wn + ni * 8 + gid) * 64 + off);
#pragma unroll
            for (int mi = 0; mi < 4; mi++)
#pragma unroll
                for (int ni = 0; ni < 4; ni++)
                    mma16h(acc[mi][ni],
                           fa[mi][0].x, fa[mi][1].x, fa[mi][0].y, fa[mi][1].y,
                           fb[ni].x, fb[ni].y);
        }
        sl    = (sl    == 2) ? 0 : sl + 1;
        sl_ld = (sl_ld == 2) ? 0 : sl_ld + 1;
    }

    // epilogue
#pragma unroll
    for (int ni = 0; ni < 4; ni++) {
        const int cb = bn + wn + ni * 8;
        const int c0 = 2 * tig, c1 = 2 * tig + 1;
        const float b0 = bias[cb + c0], b1 = bias[cb + c1];
#pragma unroll
        for (int mi = 0; mi < 4; mi++) {
            const int row = bm + wm + mi * 16 + gid;
#pragma unroll
            for (int rr = 0; rr < 2; rr++) {
                const int r = row + rr * 8;
                float v0 = acc[mi][ni][rr * 2 + 0] + b0;
                float v1 = acc[mi][ni][rr * 2 + 1] + b1;
                size_t off = (size_t)r * N + cb + c0;
                if (RES) { v0 += res[off]; v1 += res[off + 1]; }
                if (RELU) { v0 = fmaxf(v0, 0.f); v1 = fmaxf(v1, 0.f); }
                if (OUT == 0) {
                    float2 o; o.x = v0; o.y = v1;
                    *(float2*)&((float*)Cv)[off] = o;
                } else if (OUT == 1) {
                    __half* C16 = (__half*)Cv;
                    int col0 = cb + c0;
                    size_t idx = (size_t)r * N + (col0 & ~15) + p16(col0 & 15);
                    *(__half2*)&C16[idx] = __floats2half2_rn(v0, v1);
                } else {
                    int col0 = cb + c0;
                    __half h0 = __float2half_rn(v0), h1v = __float2half_rn(v1);
                    if (col0 < 2048) {
                        size_t idx = (size_t)r * 2048 + (col0 & ~15) + p16(col0 & 15);
                        *(__half2*)&QKo[idx] = __halves2half2(h0, h1v);
                    } else {
                        int d0 = col0 - 2048;
                        int hd = d0 >> 6, dh = d0 & 63;
                        int b_ = r >> 11, l = r & 2047;
                        size_t lidx = (size_t)(l & ~15) + p16(l & 15);
                        size_t rowb = ((size_t)(b_ * HH + hd) * DHD + dh) * LL;
                        VTo[rowb + lidx]      = h0;
                        VTo[rowb + LL + lidx] = h1v;   // dh+1 (dh even)
                    }
                }
            }
        }
    }
}

// ============================================================
// FP16 tensor-core causal flash attention. (unchanged from R16)
// ============================================================
#define AQ 128

__global__ void __launch_bounds__(256) attn_h(
    const __half* __restrict__ qk, const __half* __restrict__ vt,
    __half* __restrict__ O)
{
    __shared__ __half Qs[128 * 64];
    __shared__ __half Ks[2][32 * 64];
    __shared__ __half Vts[2][64 * 32];
    __shared__ __half Ps[128 * 32];

    const int qi = (int)gridDim.x - 1 - (int)blockIdx.x;   // heavy-first
    const int h = blockIdx.y, b = blockIdx.z;
    const int tid = threadIdx.x, lane = tid & 31, wid = tid >> 5;
    const int gid = lane >> 2, tig = lane & 3;

    const uint32_t sQ = (uint32_t)__cvta_generic_to_shared(Qs);
    const uint32_t sK = (uint32_t)__cvta_generic_to_shared(Ks);
    const uint32_t sV = (uint32_t)__cvta_generic_to_shared(Vts);

    const __half* qbQ = qk + ((size_t)(b * LL + qi * AQ)) * 2048 + h * 64;
    const __half* qbK = qk + ((size_t)(b * LL)) * 2048 + 1024 + h * 64;
    const __half* vb  = vt + ((size_t)(b * HH + h) * DHD) * LL;

#pragma unroll
    for (int i = 0; i < 4; i++) {
        int c = tid + i * 256;
        int r = c >> 3, ch = c & 7;
        uint32_t dst = sQ + (uint32_t)(r * 128 + (((ch >> 1) ^ (r & 3)) * 32) + (ch & 1) * 16);
        cp_async16(dst, qbQ + (size_t)r * 2048 + ch * 8);
    }
    cp_commit();
    auto load_kv = [&](int kt, int slot) {
        {
            int r = tid >> 3, ch = tid & 7;
            uint32_t dst = sK + (uint32_t)(slot * 4096 + r * 128 + (((ch >> 1) ^ (r & 3)) * 32) + (ch & 1) * 16);
            cp_async16(dst, qbK + (size_t)(kt * 32 + r) * 2048 + ch * 8);
        }
        {
            int d = tid >> 2, ch = tid & 3;
            uint32_t dst = sV + (uint32_t)(slot * 4096 + d * 64 + (((ch >> 1) ^ ((d >> 1) & 1)) * 32) + (ch & 1) * 16);
            cp_async16(dst, vb + (size_t)d * LL + kt * 32 + ch * 8);
        }
    };
    load_kv(0, 0); cp_commit();

    float m0 = -1e30f, m1 = -1e30f, l0 = 0.f, l1 = 0.f;
    float oacc[8][4];
#pragma unroll
    for (int ni = 0; ni < 8; ni++)
#pragma unroll
        for (int c = 0; c < 4; c++) oacc[ni][c] = 0.f;

    const int r0 = 16 * wid + gid;
    const int rowg0 = qi * AQ + r0, rowg1 = rowg0 + 8;
    const int keyQ = r0 & 3;
    const int keyP = (r0 >> 1) & 1;
    const int ktmax = 4 * qi + 3;

    cp_wait<1>();
    __syncthreads();
    uint2 qfa[4][2];
#pragma unroll
    for (int grp = 0; grp < 4; grp++) {
        const __half* qa = Qs + r0 * 64 + ((grp ^ keyQ) * 16) + tig * 4;
        qfa[grp][0] = *(const uint2*)qa;
        qfa[grp][1] = *(const uint2*)(qa + 8 * 64);
    }

    for (int kt = 0; kt <= ktmax; kt++) {
        cp_wait<0>();
        __syncthreads();
        if (kt + 1 <= ktmax) load_kv(kt + 1, (kt + 1) & 1);
        cp_commit();

        const __half* Kt  = Ks[kt & 1];
        const __half* Vtt = Vts[kt & 1];

        float sfr[4][4];
#pragma unroll
        for (int ni = 0; ni < 4; ni++)
#pragma unroll
            for (int c = 0; c < 4; c++) sfr[ni][c] = 0.f;
#pragma unroll
        for (int grp = 0; grp < 4; grp++) {
#pragma unroll
            for (int ni = 0; ni < 4; ni++) {
                int kk = 8 * ni + gid;
                uint2 fb = *(const uint2*)(Kt + kk * 64 + ((grp ^ (kk & 3)) * 16) + tig * 4);
                mma16h(sfr[ni], qfa[grp][0].x, qfa[grp][1].x,
                       qfa[grp][0].y, qfa[grp][1].y, fb.x, fb.y);
            }
        }

        const bool domask = (kt >= 4 * qi);
        const int colbase = kt * 32;
        float p[4][4];
#pragma unroll
        for (int ni = 0; ni < 4; ni++)
#pragma unroll
            for (int c = 0; c < 4; c++) {
                float v = sfr[ni][c] * 0.125f;
                if (domask) {
                    int col = colbase + 8 * ni + 2 * tig + (c & 1);
                    int rg = (c < 2) ? rowg0 : rowg1;
                    if (col > rg) v = -1e30f;
                }
                p[ni][c] = v;
            }
#pragma unroll
        for (int half = 0; half < 2; half++) {
            float rmax = -1e30f;
#pragma unroll
            for (int ni = 0; ni < 4; ni++) {
                rmax = fmaxf(rmax, p[ni][half * 2]);
                rmax = fmaxf(rmax, p[ni][half * 2 + 1]);
            }
            rmax = fmaxf(rmax, __shfl_xor_sync(0xffffffffu, rmax, 1));
            rmax = fmaxf(rmax, __shfl_xor_sync(0xffffffffu, rmax, 2));
            float mprev = half ? m1 : m0;
            float mn = fmaxf(mprev, rmax);
            float alpha = __expf(mprev - mn);
            float psum = 0.f;
#pragma unroll
            for (int ni = 0; ni < 4; ni++) {
#pragma unroll
                for (int j = 0; j < 2; j++) {
                    float e = __expf(p[ni][half * 2 + j] - mn);
                    p[ni][half * 2 + j] = e;
                    psum += e;
                }
            }
            psum += __shfl_xor_sync(0xffffffffu, psum, 1);
            psum += __shfl_xor_sync(0xffffffffu, psum, 2);
            if (half == 0) { l0 = l0 * alpha + psum; m0 = mn; }
            else           { l1 = l1 * alpha + psum; m1 = mn; }
#pragma unroll
            for (int ni = 0; ni < 8; ni++) {
                oacc[ni][half * 2]     *= alpha;
                oacc[ni][half * 2 + 1] *= alpha;
            }
        }

#pragma unroll
        for (int ni = 0; ni < 4; ni++) {
            int g16 = ni >> 1;
            int off0 = r0 * 32 + ((g16 ^ keyP) * 16) + 4 * tig + 2 * (ni & 1);
            *(__half2*)(Ps + off0)          = __floats2half2_rn(p[ni][0], p[ni][1]);
            *(__half2*)(Ps + off0 + 8 * 32) = __floats2half2_rn(p[ni][2], p[ni][3]);
        }
        __syncwarp();

#pragma unroll
        for (int grp = 0; grp < 2; grp++) {
            const __half* pa = Ps + r0 * 32 + ((grp ^ keyP) * 16) + tig * 4;
            uint2 fa0 = *(const uint2*)pa;
            uint2 fa1 = *(const uint2*)(pa + 8 * 32);
#pragma unroll
            for (int ni = 0; ni < 8; ni++) {
                int dd = 8 * ni + gid;
                uint2 fb = *(const uint2*)(Vtt + dd * 32 + ((grp ^ ((dd >> 1) & 1)) * 16) + tig * 4);
                mma16h(oacc[ni], fa0.x, fa1.x, fa0.y, fa1.y, fb.x, fb.y);
            }
        }
    }

    float inv0 = 1.0f / l0, inv1 = 1.0f / l1;
    size_t ob0 = ((size_t)(b * LL + rowg0) * HH + h) * DHD;
    size_t ob1 = ((size_t)(b * LL + rowg1) * HH + h) * DHD;
#pragma unroll
    for (int ni = 0; ni < 8; ni++) {
        int dcol = 8 * ni + 2 * tig;
        int pos = (dcol & ~15) + p16(dcol & 15);
        *(__half2*)&O[ob0 + pos] = __floats2half2_rn(oacc[ni][0] * inv0, oacc[ni][1] * inv0);
        *(__half2*)&O[ob1 + pos] = __floats2half2_rn(oacc[ni][2] * inv1, oacc[ni][3] * inv1);
    }
}

// ============================================================
// LayerNorm (ddof=1, (std+eps)); optional fp16-permuted 2nd output
// ============================================================
__global__ void __launch_bounds__(256) ln_kernel(
    const float* __restrict__ X, const float* __restrict__ gamma,
    const float* __restrict__ beta, float* __restrict__ Y,
    __half* __restrict__ Yr)
{
    const int row = blockIdx.x;
    const int tid = threadIdx.x;
    const int lane = tid & 31, wid = tid >> 5;
    __shared__ float red[8];

    float4 v = *(const float4*)&X[(size_t)row * DD + tid * 4];

    float s = v.x + v.y + v.z + v.w;
#pragma unroll
    for (int off = 16; off > 0; off >>= 1) s += __shfl_xor_sync(0xffffffffu, s, off);
    if (lane == 0) red[wid] = s;
    __syncthreads();
    float mean = 0.f;
#pragma unroll
    for (int i = 0; i < 8; i++) mean += red[i];
    mean *= (1.0f / 1024.f);
    __syncthreads();

    float dx = v.x - mean, dy = v.y - mean, dz = v.z - mean, dw = v.w - mean;
    float ss = dx*dx + dy*dy + dz*dz + dw*dw;
#pragma unroll
    for (int off = 16; off > 0; off >>= 1) ss += __shfl_xor_sync(0xffffffffu, ss, off);
    if (lane == 0) red[wid] = ss;
    __syncthreads();
    float var = 0.f;
#pragma unroll
    for (int i = 0; i < 8; i++) var += red[i];
    var *= (1.0f / 1023.f);
    float istd = 1.0f / (sqrtf(var) + 1e-6f);

    float4 g  = *(const float4*)&gamma[tid * 4];
    float4 bb = *(const float4*)&beta[tid * 4];
    float o[4];
    o[0] = dx * istd * g.x + bb.x;
    o[1] = dy * istd * g.y + bb.y;
    o[2] = dz * istd * g.z + bb.z;
    o[3] = dw * istd * g.w + bb.w;
    float4 outv; outv.x = o[0]; outv.y = o[1]; outv.z = o[2]; outv.w = o[3];
    *(float4*)&Y[(size_t)row * DD + tid * 4] = outv;
    if (Yr) {
        __half* yr = Yr + (size_t)row * DD;
#pragma unroll
        for (int e = 0; e < 4; e++) {
            int col = tid * 4 + e;
            yr[(col & ~15) + p16(col & 15)] = __float2half_rn(o[e]);
        }
    }
}

// ============================================================
extern "C" void kernel_launch(void* const* d_in, const int* in_sizes, int n_in,
                              void* d_out, int out_size)
{
    const float* x     = (const float*)d_in[0];
    const float* Wqkv  = (const float*)d_in[2];
    const float* bqkv  = (const float*)d_in[3];
    const float* Wo    = (const float*)d_in[4];
    const float* bo    = (const float*)d_in[5];
    const float* ln1_a = (const float*)d_in[6];
    const float* ln1_b = (const float*)d_in[7];
    const float* W1    = (const float*)d_in[8];
    const float* b1    = (const float*)d_in[9];
    const float* W2    = (const float*)d_in[10];
    const float* b2    = (const float*)d_in[11];
    const float* ln2_a = (const float*)d_in[12];
    const float* ln2_b = (const float*)d_in[13];
    float* out = (float*)d_out;

    float  *t0, *h1;
    __half *qkb, *vtb, *attn, *h1r, *ffn, *xr, *wqkvr, *wor, *w1r, *w2r;
    cudaGetSymbolAddress((void**)&qkb,   g_qk);
    cudaGetSymbolAddress((void**)&vtb,   g_vt);
    cudaGetSymbolAddress((void**)&attn,  g_attn);
    cudaGetSymbolAddress((void**)&t0,    g_t0);
    cudaGetSymbolAddress((void**)&h1,    g_h1);
    cudaGetSymbolAddress((void**)&h1r,   g_h1r);
    cudaGetSymbolAddress((void**)&ffn,   g_ffn);
    cudaGetSymbolAddress((void**)&xr,    g_xr);
    cudaGetSymbolAddress((void**)&wqkvr, g_wqkvr);
    cudaGetSymbolAddress((void**)&wor,   g_wor);
    cudaGetSymbolAddress((void**)&w1r,   g_w1r);
    cudaGetSymbolAddress((void**)&w2r,   g_w2r);

    cudaFuncSetAttribute(gemm_h<false,false,2>, cudaFuncAttributeMaxDynamicSharedMemorySize, GEMM_SMEM);
    cudaFuncSetAttribute(gemm_h<false,true ,0>, cudaFuncAttributeMaxDynamicSharedMemorySize, GEMM_SMEM);
    cudaFuncSetAttribute(gemm_h<true ,false,1>, cudaFuncAttributeMaxDynamicSharedMemorySize, GEMM_SMEM);

    dim3 blk(256);

    // 0) single fused convert+permute for all operands
    fused_conv<<<CONV_TOTAL / 512, blk>>>(x, xr, Wqkv, wqkvr, Wo, wor, W1, w1r, W2, w2r);

    // 1) QKV GEMM: Q/K -> g_qk (fp16 perm16), V -> g_vt (fp16 transposed)
    gemm_h<false,false,2><<<dim3(3072/128, MTOT/128), blk, GEMM_SMEM>>>(
        xr, wqkvr, bqkv, nullptr, nullptr, qkb, vtb, MTOT, 3*DD, DD);

    // 2) fp16 tensor-core causal flash attention -> attn (fp16 perm16)
    attn_h<<<dim3(LL/AQ, HH, BBAT), blk>>>(qkb, vtb, attn);

    // 3) t0 = attn @ Wo^T + bo + x (fp32 out)
    gemm_h<false,true,0><<<dim3(DD/128, MTOT/128), blk, GEMM_SMEM>>>(
        attn, wor, bo, x, t0, nullptr, nullptr, MTOT, DD, DD);

    // 4) h1 = LN1(t0) fp32, h1r fp16 perm16
    ln_kernel<<<MTOT, blk>>>(t0, ln1_a, ln1_b, h1, h1r);

    // 5) ffn = relu(h1r @ W1^T + b1) (fp16 perm16 out)
    gemm_h<true,false,1><<<dim3(DFFN/128, MTOT/128), blk, GEMM_SMEM>>>(
        h1r, w1r, b1, nullptr, ffn, nullptr, nullptr, MTOT, DFFN, DD);

    // 6) t0 = ffn @ W2^T + b2 + h1 (fp32 out)
    gemm_h<false,true,0><<<dim3(DD/128, MTOT/128), blk, GEMM_SMEM>>>(
        ffn, w2r, b2, h1, t0, nullptr, nullptr, MTOT, DD, DFFN);

    // 7) out = LN2(t0)
    ln_kernel<<<MTOT, blk>>>(t0, ln2_a, ln2_b, out, nullptr);
}